// round 8
// baseline (speedup 1.0000x reference)
#include <cuda_runtime.h>
#include <cuda_bf16.h>
#include <math.h>
#include <stdint.h>

#define B_   64
#define Q_   64
#define T_   448
#define D_   512
#define FD_  1024
#define H_   8
#define DH_  64
#define FF_  2048
#define S_   512
#define BS_  (B_ * S_)   // 32768
#define BT_  (B_ * T_)   // 28672
#define LDQKV 1536

// ---------------- scratch (static device globals; no allocation) ----------------
__device__ float g_x[BS_ * D_];
__device__ float g_qkv[(size_t)BS_ * LDQKV];
__device__ float g_y[BS_ * D_];
__device__ float g_vproj[(size_t)BT_ * D_];
__device__ float g_bqkv[2 * LDQKV];

// bf16 hi/lo split activations
__device__ __nv_bfloat16 g_xh[BS_ * D_], g_xl[BS_ * D_];
__device__ __nv_bfloat16 g_ch[BS_ * D_], g_cl[BS_ * D_];
__device__ __nv_bfloat16 g_hh[(size_t)BS_ * FF_], g_hl[(size_t)BS_ * FF_];
__device__ __nv_bfloat16 g_vh[(size_t)BT_ * FD_], g_vl[(size_t)BT_ * FD_];

// split/transposed weights: hi + lo bf16, layout [N][K]
#define WSPLIT_TOTAL 6815744
__device__ __nv_bfloat16 g_wh[WSPLIT_TOTAL];
__device__ __nv_bfloat16 g_wl[WSPLIT_TOTAL];

// ---------------- small helpers ----------------
__device__ __forceinline__ float4 ld4(const float* p) { return *(const float4*)p; }
__device__ __forceinline__ void st4(float* p, float4 v) { *(float4*)p = v; }

__device__ __forceinline__ void split_store4(__nv_bfloat16* __restrict__ hp,
                                             __nv_bfloat16* __restrict__ lp,
                                             size_t off, float4 v) {
    __nv_bfloat16 h0 = __float2bfloat16(v.x);
    __nv_bfloat16 h1 = __float2bfloat16(v.y);
    __nv_bfloat16 h2 = __float2bfloat16(v.z);
    __nv_bfloat16 h3 = __float2bfloat16(v.w);
    __nv_bfloat16 l0 = __float2bfloat16(v.x - __bfloat162float(h0));
    __nv_bfloat16 l1 = __float2bfloat16(v.y - __bfloat162float(h1));
    __nv_bfloat16 l2 = __float2bfloat16(v.z - __bfloat162float(h2));
    __nv_bfloat16 l3 = __float2bfloat16(v.w - __bfloat162float(h3));
    *(__nv_bfloat162*)(hp + off)     = __nv_bfloat162(h0, h1);
    *(__nv_bfloat162*)(hp + off + 2) = __nv_bfloat162(h2, h3);
    *(__nv_bfloat162*)(lp + off)     = __nv_bfloat162(l0, l1);
    *(__nv_bfloat162*)(lp + off + 2) = __nv_bfloat162(l2, l3);
}

__device__ __forceinline__ float block_sum(float v, float* sm) {
#pragma unroll
    for (int o = 16; o; o >>= 1) v += __shfl_xor_sync(0xffffffffu, v, o);
    int w = threadIdx.x >> 5;
    __syncthreads();
    if ((threadIdx.x & 31) == 0) sm[w] = v;
    __syncthreads();
    return (sm[0] + sm[1]) + (sm[2] + sm[3]);
}

__device__ __forceinline__ void block_ln(float4& v, int i0,
                                         const float* __restrict__ g,
                                         const float* __restrict__ b,
                                         float* sm) {
    float s = v.x + v.y + v.z + v.w;
    s = block_sum(s, sm);
    float mean = s * (1.0f / (float)D_);
    float dx = v.x - mean, dy = v.y - mean, dz = v.z - mean, dw = v.w - mean;
    float ss = dx * dx + dy * dy + dz * dz + dw * dw;
    ss = block_sum(ss, sm);
    float inv = rsqrtf(ss * (1.0f / (float)D_) + 1e-12f);
    float4 gg = ld4(g + i0), bb = ld4(b + i0);
    v.x = dx * inv * gg.x + bb.x;
    v.y = dy * inv * gg.y + bb.y;
    v.z = dz * inv * gg.z + bb.z;
    v.w = dw * inv * gg.w + bb.w;
}

// ---------------- weight transpose+split: T[n][k] = W[k][n] as bf16 hi/lo ----------------
__global__ void split_w_kernel(const float* __restrict__ W, int K, int N,
                               __nv_bfloat16* __restrict__ Th, __nv_bfloat16* __restrict__ Tl) {
    __shared__ float tile[32][33];
    int k0 = blockIdx.y * 32, n0 = blockIdx.x * 32;
    int tx = threadIdx.x, ty = threadIdx.y;
    for (int j = ty; j < 32; j += 8)
        tile[j][tx] = W[(size_t)(k0 + j) * N + n0 + tx];
    __syncthreads();
    for (int j = ty; j < 32; j += 8) {
        float v = tile[tx][j];
        __nv_bfloat16 hi = __float2bfloat16(v);
        __nv_bfloat16 lo = __float2bfloat16(v - __bfloat162float(hi));
        size_t o = (size_t)(n0 + j) * K + k0 + tx;
        Th[o] = hi; Tl[o] = lo;
    }
}

// ---------------- plain elementwise split (video) ----------------
__global__ void split_a_kernel(const float* __restrict__ A,
                               __nv_bfloat16* __restrict__ Ah, __nv_bfloat16* __restrict__ Al) {
    size_t i = ((size_t)blockIdx.x * 256 + threadIdx.x) * 4;
    float4 v = ld4(A + i);
    split_store4(Ah, Al, i, v);
}

// ---------------- concat qkv bias ----------------
__global__ void concat_bias_kernel(const float* __restrict__ bq, const float* __restrict__ bk,
                                   const float* __restrict__ bv, float* __restrict__ dst) {
    int i = blockIdx.x * 256 + threadIdx.x;
    if (i < LDQKV)
        dst[i] = (i < 512) ? bq[i] : ((i < 1024) ? bk[i - 512] : bv[i - 1024]);
}

// ---------------- mma.sync GEMM: presplit bf16, 4-stage cp.async pipeline ----------------
// C = epilogue(A @ W^T + bias); A presplit [M][K] hi/lo, W presplit [N][K] hi/lo
// MODE 0: f32 out, cols < scale_cols multiplied by scale
// MODE 2: gelu -> bf16 hi/lo split out
#define GLDA 40
#define ARR  (128 * GLDA)
#define BUFE (4 * ARR)
#define NSTAGE 4
#define GT2_SMEM (NSTAGE * BUFE * 2)   // 163840 bytes

__device__ __forceinline__ void mma16816(float* d, const unsigned* a, const unsigned* b) {
    asm volatile(
        "mma.sync.aligned.m16n8k16.row.col.f32.bf16.bf16.f32 "
        "{%0,%1,%2,%3}, {%4,%5,%6,%7}, {%8,%9}, {%0,%1,%2,%3};\n"
        : "+f"(d[0]), "+f"(d[1]), "+f"(d[2]), "+f"(d[3])
        : "r"(a[0]), "r"(a[1]), "r"(a[2]), "r"(a[3]), "r"(b[0]), "r"(b[1]));
}
__device__ __forceinline__ void ldsm4(unsigned* r, unsigned addr) {
    asm volatile("ldmatrix.sync.aligned.m8n8.x4.shared.b16 {%0,%1,%2,%3}, [%4];\n"
                 : "=r"(r[0]), "=r"(r[1]), "=r"(r[2]), "=r"(r[3]) : "r"(addr));
}
__device__ __forceinline__ void ldsm2(unsigned* r, unsigned addr) {
    asm volatile("ldmatrix.sync.aligned.m8n8.x2.shared.b16 {%0,%1}, [%2];\n"
                 : "=r"(r[0]), "=r"(r[1]) : "r"(addr));
}
__device__ __forceinline__ void cpasync16(uint32_t dst, const void* src) {
    asm volatile("cp.async.cg.shared.global [%0], [%1], 16;" :: "r"(dst), "l"(src));
}
#define CP_COMMIT() asm volatile("cp.async.commit_group;" ::: "memory")
#define CP_WAIT2()  asm volatile("cp.async.wait_group 2;" ::: "memory")
#define CP_WAIT1()  asm volatile("cp.async.wait_group 1;" ::: "memory")
#define CP_WAIT0()  asm volatile("cp.async.wait_group 0;" ::: "memory")

template<int MODE>
__global__ __launch_bounds__(256, 1)
void gemm_bf16(const __nv_bfloat16* __restrict__ Ah_g, const __nv_bfloat16* __restrict__ Al_g,
               const __nv_bfloat16* __restrict__ Wh_g, const __nv_bfloat16* __restrict__ Wl_g,
               const float* __restrict__ bias,
               float* __restrict__ C,
               __nv_bfloat16* __restrict__ Ch, __nv_bfloat16* __restrict__ Cl,
               int M, int N, int K, float scale, int scale_cols) {
    extern __shared__ __nv_bfloat16 smg[];

    int tid = threadIdx.x;
    int lane = tid & 31, wid = tid >> 5;
    int warpM = wid & 1, warpN = wid >> 1;
    int m0 = warpM * 64, n0 = warpN * 32;

    int blockM = blockIdx.y * 128;
    int blockN = blockIdx.x * 128;

    int a_row = lane & 15, a_cs = (lane >> 4) * 8;
    int b_row = lane & 7,  b_cs = ((lane >> 3) & 1) * 8;

    float acc[4][4][4];
#pragma unroll
    for (int f = 0; f < 4; ++f)
#pragma unroll
        for (int g = 0; g < 4; ++g)
#pragma unroll
            for (int j = 0; j < 4; ++j) acc[f][g][j] = 0.0f;

    int sr[2], sc[2];
#pragma unroll
    for (int wv = 0; wv < 2; ++wv) {
        int idx = tid + wv * 256;
        sr[wv] = idx >> 2;
        sc[wv] = (idx & 3) * 8;
    }

    auto stage = [&](int kt) {
        __nv_bfloat16* base = smg + (kt & (NSTAGE - 1)) * BUFE;
#pragma unroll
        for (int wv = 0; wv < 2; ++wv) {
            int r = sr[wv], c8 = sc[wv];
            uint32_t dsm = (uint32_t)__cvta_generic_to_shared(base + r * GLDA + c8);
            size_t ga = (size_t)(blockM + r) * K + kt * 32 + c8;
            size_t gb = (size_t)(blockN + r) * K + kt * 32 + c8;
            cpasync16(dsm,               Ah_g + ga);
            cpasync16(dsm + ARR * 2,     Al_g + ga);
            cpasync16(dsm + 2 * ARR * 2, Wh_g + gb);
            cpasync16(dsm + 3 * ARR * 2, Wl_g + gb);
        }
        CP_COMMIT();
    };

    int T = K >> 5;
    stage(0);
    if (T > 1) stage(1);
    if (T > 2) stage(2);

    for (int kt = 0; kt < T; ++kt) {
        if (kt + 2 < T)      CP_WAIT2();
        else if (kt + 1 < T) CP_WAIT1();
        else                 CP_WAIT0();
        __syncthreads();
        if (kt + 3 < T) stage(kt + 3);

        __nv_bfloat16* Ahs = smg + (kt & (NSTAGE - 1)) * BUFE;
        __nv_bfloat16* Als = Ahs + ARR;
        __nv_bfloat16* Bhs = Ahs + 2 * ARR;
        __nv_bfloat16* Bls = Ahs + 3 * ARR;

#pragma unroll
        for (int kc = 0; kc < 32; kc += 16) {
            unsigned aF[16], bHf[8], bLf[8];
#pragma unroll
            for (int f = 0; f < 4; ++f)
                ldsm4(aF + 4 * f, (unsigned)__cvta_generic_to_shared(
                    Ahs + (m0 + f * 16 + a_row) * GLDA + kc + a_cs));
#pragma unroll
            for (int g = 0; g < 4; ++g)
                ldsm2(bHf + 2 * g, (unsigned)__cvta_generic_to_shared(
                    Bhs + (n0 + g * 8 + b_row) * GLDA + kc + b_cs));
#pragma unroll
            for (int g = 0; g < 4; ++g)
                ldsm2(bLf + 2 * g, (unsigned)__cvta_generic_to_shared(
                    Bls + (n0 + g * 8 + b_row) * GLDA + kc + b_cs));
#pragma unroll
            for (int f = 0; f < 4; ++f)
#pragma unroll
                for (int g = 0; g < 4; ++g)
                    mma16816(acc[f][g], aF + 4 * f, bHf + 2 * g);
#pragma unroll
            for (int f = 0; f < 4; ++f)
#pragma unroll
                for (int g = 0; g < 4; ++g)
                    mma16816(acc[f][g], aF + 4 * f, bLf + 2 * g);
#pragma unroll
            for (int f = 0; f < 4; ++f)
                ldsm4(aF + 4 * f, (unsigned)__cvta_generic_to_shared(
                    Als + (m0 + f * 16 + a_row) * GLDA + kc + a_cs));
#pragma unroll
            for (int f = 0; f < 4; ++f)
#pragma unroll
                for (int g = 0; g < 4; ++g)
                    mma16816(acc[f][g], aF + 4 * f, bHf + 2 * g);
        }
        __syncthreads();
    }

    // ---- epilogue ----
    bool do_scale = (MODE == 0) && (blockN < scale_cols);
#pragma unroll
    for (int f = 0; f < 4; ++f) {
#pragma unroll
        for (int g = 0; g < 4; ++g) {
            int col = blockN + n0 + g * 8 + (lane & 3) * 2;
            float b0 = bias[col], b1 = bias[col + 1];
#pragma unroll
            for (int half = 0; half < 2; ++half) {
                int row = blockM + m0 + f * 16 + (lane >> 2) + half * 8;
                float v0 = acc[f][g][half * 2 + 0] + b0;
                float v1 = acc[f][g][half * 2 + 1] + b1;
                if (MODE == 0) {
                    if (do_scale) { v0 *= scale; v1 *= scale; }
                    *(float2*)&C[(size_t)row * N + col] = make_float2(v0, v1);
                } else {
                    v0 = 0.5f * v0 * (1.0f + erff(v0 * 0.70710678118654752f));
                    v1 = 0.5f * v1 * (1.0f + erff(v1 * 0.70710678118654752f));
                    __nv_bfloat16 h0 = __float2bfloat16(v0);
                    __nv_bfloat16 h1 = __float2bfloat16(v1);
                    __nv_bfloat16 l0 = __float2bfloat16(v0 - __bfloat162float(h0));
                    __nv_bfloat16 l1 = __float2bfloat16(v1 - __bfloat162float(h1));
                    size_t off = (size_t)row * N + col;
                    *(__nv_bfloat162*)(Ch + off) = __nv_bfloat162(h0, h1);
                    *(__nv_bfloat162*)(Cl + off) = __nv_bfloat162(l0, l1);
                }
            }
        }
    }
}

// ---------------- build x ----------------
__global__ void build_x_kernel(const float* __restrict__ question,
                               const float* __restrict__ vproj,
                               const float* __restrict__ pos_emb,
                               const float* __restrict__ mod_emb,
                               const float* __restrict__ nv_g, const float* __restrict__ nv_b,
                               const float* __restrict__ emb_g, const float* __restrict__ emb_b,
                               float* __restrict__ x,
                               __nv_bfloat16* __restrict__ xh, __nv_bfloat16* __restrict__ xl) {
    __shared__ float sm[4];
    int row = blockIdx.x;
    int b = row / S_, s = row % S_;
    int i0 = threadIdx.x * 4;
    float4 v;
    if (s < Q_) {
        v = ld4(question + ((size_t)b * Q_ + s) * D_ + i0);
    } else {
        v = ld4(vproj + ((size_t)b * T_ + (s - Q_)) * D_ + i0);
        block_ln(v, i0, nv_g, nv_b, sm);
    }
    float4 pe = ld4(pos_emb + (size_t)s * D_ + i0);
    const float* me_p = mod_emb + (size_t)(s < Q_ ? 0 : 1) * D_ + i0;
    float4 me = ld4(me_p);
    v.x += pe.x + me.x; v.y += pe.y + me.y; v.z += pe.z + me.z; v.w += pe.w + me.w;
    block_ln(v, i0, emb_g, emb_b, sm);
    size_t off = (size_t)row * D_ + i0;
    st4(x + off, v);
    split_store4(xh, xl, off, v);
}

// ---------------- residual + LN ----------------
__global__ void add_ln_kernel(const float* __restrict__ y, const float* __restrict__ res,
                              float* __restrict__ out,
                              __nv_bfloat16* __restrict__ oh, __nv_bfloat16* __restrict__ ol,
                              const float* __restrict__ g, const float* __restrict__ bta) {
    __shared__ float sm[4];
    int row = blockIdx.x;
    int i0 = threadIdx.x * 4;
    size_t off = (size_t)row * D_ + i0;
    float4 a = ld4(y + off), r = ld4(res + off);
    float4 v = make_float4(a.x + r.x, a.y + r.y, a.z + r.z, a.w + r.w);
    block_ln(v, i0, g, bta, sm);
    st4(out + off, v);
    split_store4(oh, ol, off, v);
}

// ---------------- tiled flash attention (reads fused qkv, stride LDQKV) ----------------
__device__ __forceinline__ float4* tsl(float4* base, int r, int c4) {
    return base + r * 16 + ((c4 + (r >> 2)) & 15);
}

__global__ __launch_bounds__(256)
void attn_tile_kernel(const float* __restrict__ qkv, const int* __restrict__ mask,
                      __nv_bfloat16* __restrict__ ch, __nv_bfloat16* __restrict__ cl) {
    extern __shared__ float smdyn[];
    float4* Qs = (float4*)smdyn;
    float4* KP = Qs + 1024;
    float4* Vs = KP + 1024;
    __shared__ int ms[64];

    int bh = blockIdx.x;
    int b = bh >> 3, h = bh & 7;
    int q0 = blockIdx.y * 64;
    int tid = threadIdx.x;
    int tx = tid & 15, ty = tid >> 4;

    const float* qb = qkv + (size_t)b * S_ * LDQKV + h * DH_;
    const float* kb = qb + 512;
    const float* vb = qb + 1024;

    {
        int r = tid >> 2, c4 = (tid & 3) * 4;
        const float* src = qb + (size_t)(q0 + r) * LDQKV + c4 * 4;
#pragma unroll
        for (int u = 0; u < 4; ++u)
            *tsl(Qs, r, c4 + u) = ld4(src + u * 4);
    }

    float m[4], l[4], o[4][4];
#pragma unroll
    for (int i = 0; i < 4; ++i) {
        m[i] = -INFINITY; l[i] = 0.0f;
#pragma unroll
        for (int c = 0; c < 4; ++c) o[i][c] = 0.0f;
    }

    for (int kt = 0; kt < 8; ++kt) {
        int k0 = kt * 64;
        __syncthreads();
        {
            int r = tid >> 2, c4 = (tid & 3) * 4;
            const float* ks = kb + (size_t)(k0 + r) * LDQKV + c4 * 4;
            const float* vs = vb + (size_t)(k0 + r) * LDQKV + c4 * 4;
#pragma unroll
            for (int u = 0; u < 4; ++u) {
                *tsl(KP, r, c4 + u) = ld4(ks + u * 4);
                *tsl(Vs, r, c4 + u) = ld4(vs + u * 4);
            }
            if (tid < 64) ms[tid] = mask[b * S_ + k0 + tid];
        }
        __syncthreads();

        float s[4][4];
#pragma unroll
        for (int i = 0; i < 4; ++i)
#pragma unroll
            for (int j = 0; j < 4; ++j) s[i][j] = 0.0f;

        for (int d4 = 0; d4 < 16; ++d4) {
            float4 qv[4], kv[4];
#pragma unroll
            for (int i = 0; i < 4; ++i) qv[i] = *tsl(Qs, ty * 4 + i, d4);
#pragma unroll
            for (int j = 0; j < 4; ++j) kv[j] = *tsl(KP, tx * 4 + j, d4);
#pragma unroll
            for (int i = 0; i < 4; ++i)
#pragma unroll
                for (int j = 0; j < 4; ++j) {
                    s[i][j] = fmaf(qv[i].x, kv[j].x, s[i][j]);
                    s[i][j] = fmaf(qv[i].y, kv[j].y, s[i][j]);
                    s[i][j] = fmaf(qv[i].z, kv[j].z, s[i][j]);
                    s[i][j] = fmaf(qv[i].w, kv[j].w, s[i][j]);
                }
        }
#pragma unroll
        for (int j = 0; j < 4; ++j) {
            if (ms[tx * 4 + j] == 0) {
#pragma unroll
                for (int i = 0; i < 4; ++i) s[i][j] = -INFINITY;
            }
        }

        float p[4][4], corr[4], psum[4];
#pragma unroll
        for (int i = 0; i < 4; ++i) {
            float rm = fmaxf(fmaxf(s[i][0], s[i][1]), fmaxf(s[i][2], s[i][3]));
#pragma unroll
            for (int off = 1; off < 16; off <<= 1)
                rm = fmaxf(rm, __shfl_xor_sync(0xffffffffu, rm, off));
            float nm = fmaxf(m[i], rm);
            if (nm == -INFINITY) {
                corr[i] = 1.0f;
#pragma unroll
                for (int j = 0; j < 4; ++j) p[i][j] = 0.0f;
            } else {
                corr[i] = __expf(m[i] - nm);
#pragma unroll
                for (int j = 0; j < 4; ++j) p[i][j] = __expf(s[i][j] - nm);
                m[i] = nm;
            }
            float ps = (p[i][0] + p[i][1]) + (p[i][2] + p[i][3]);
#pragma unroll
            for (int off = 1; off < 16; off <<= 1)
                ps += __shfl_xor_sync(0xffffffffu, ps, off);
            psum[i] = ps;
        }

        __syncthreads();
#pragma unroll
        for (int i = 0; i < 4; ++i) {
            int r = ty * 4 + i;
            float* dst = (float*)(KP + r * 16 + ((tx + (r >> 2)) & 15));
#pragma unroll
            for (int j = 0; j < 4; ++j) dst[j] = p[i][j];
        }
#pragma unroll
        for (int i = 0; i < 4; ++i) {
            l[i] = l[i] * corr[i] + psum[i];
#pragma unroll
            for (int c = 0; c < 4; ++c) o[i][c] *= corr[i];
        }
        __syncthreads();

        for (int kk4 = 0; kk4 < 16; ++kk4) {
            float4 pv[4], vv[4];
#pragma unroll
            for (int i = 0; i < 4; ++i) pv[i] = *tsl(KP, ty * 4 + i, kk4);
#pragma unroll
            for (int u = 0; u < 4; ++u) vv[u] = *tsl(Vs, kk4 * 4 + u, tx);
#pragma unroll
            for (int i = 0; i < 4; ++i) {
                o[i][0] = fmaf(pv[i].x, vv[0].x, o[i][0]);
                o[i][1] = fmaf(pv[i].x, vv[0].y, o[i][1]);
                o[i][2] = fmaf(pv[i].x, vv[0].z, o[i][2]);
                o[i][3] = fmaf(pv[i].x, vv[0].w, o[i][3]);
                o[i][0] = fmaf(pv[i].y, vv[1].x, o[i][0]);
                o[i][1] = fmaf(pv[i].y, vv[1].y, o[i][1]);
                o[i][2] = fmaf(pv[i].y, vv[1].z, o[i][2]);
                o[i][3] = fmaf(pv[i].y, vv[1].w, o[i][3]);
                o[i][0] = fmaf(pv[i].z, vv[2].x, o[i][0]);
                o[i][1] = fmaf(pv[i].z, vv[2].y, o[i][1]);
                o[i][2] = fmaf(pv[i].z, vv[2].z, o[i][2]);
                o[i][3] = fmaf(pv[i].z, vv[2].w, o[i][3]);
                o[i][0] = fmaf(pv[i].w, vv[3].x, o[i][0]);
                o[i][1] = fmaf(pv[i].w, vv[3].y, o[i][1]);
                o[i][2] = fmaf(pv[i].w, vv[3].z, o[i][2]);
                o[i][3] = fmaf(pv[i].w, vv[3].w, o[i][3]);
            }
        }
    }

#pragma unroll
    for (int i = 0; i < 4; ++i) {
        float inv = (l[i] > 0.0f) ? (1.0f / l[i]) : 0.0f;
        float4 r = make_float4(o[i][0] * inv, o[i][1] * inv, o[i][2] * inv, o[i][3] * inv);
        size_t off = (size_t)(b * S_ + q0 + ty * 4 + i) * D_ + h * DH_ + tx * 4;
        split_store4(ch, cl, off, r);
    }
}

#define ATT_SMEM (3 * 64 * 16 * 16)   // 49152 bytes

// ---------------- launcher ----------------
extern "C" void kernel_launch(void* const* d_in, const int* in_sizes, int n_in,
                              void* d_out, int out_size) {
    const float* video    = (const float*)d_in[0];
    const float* question = (const float*)d_in[1];
    const int*   mask     = (const int*)d_in[2];
    const float* pos_emb  = (const float*)d_in[3];
    const float* mod_emb  = (const float*)d_in[4];
    const float* Wv   = (const float*)d_in[5];
    const float* bv   = (const float*)d_in[6];
    const float* nv_g = (const float*)d_in[7];
    const float* nv_b = (const float*)d_in[8];
    const float* emb_g = (const float*)d_in[9];
    const float* emb_b = (const float*)d_in[10];
    const float* Wq  = (const float*)d_in[11];
    const float* bq  = (const float*)d_in[12];
    const float* Wk  = (const float*)d_in[13];
    const float* bk  = (const float*)d_in[14];
    const float* Wva = (const float*)d_in[15];
    const float* bva = (const float*)d_in[16];
    const float* Wo  = (const float*)d_in[17];
    const float* bo  = (const float*)d_in[18];
    const float* ln1_g = (const float*)d_in[19];
    const float* ln1_b = (const float*)d_in[20];
    const float* W1  = (const float*)d_in[21];
    const float* b1  = (const float*)d_in[22];
    const float* W2  = (const float*)d_in[23];
    const float* b2  = (const float*)d_in[24];
    const float* ln2_g = (const float*)d_in[25];
    const float* ln2_b = (const float*)d_in[26];
    float* out = (float*)d_out;

    float *x, *qkv, *yb, *vproj, *bqkv;
    __nv_bfloat16 *wh, *wl, *xh, *xl, *ch, *cl, *hh, *hl, *vh, *vl;
    cudaGetSymbolAddress((void**)&x,     g_x);
    cudaGetSymbolAddress((void**)&qkv,   g_qkv);
    cudaGetSymbolAddress((void**)&yb,    g_y);
    cudaGetSymbolAddress((void**)&vproj, g_vproj);
    cudaGetSymbolAddress((void**)&bqkv,  g_bqkv);
    cudaGetSymbolAddress((void**)&wh,    g_wh);
    cudaGetSymbolAddress((void**)&wl,    g_wl);
    cudaGetSymbolAddress((void**)&xh,    g_xh);
    cudaGetSymbolAddress((void**)&xl,    g_xl);
    cudaGetSymbolAddress((void**)&ch,    g_ch);
    cudaGetSymbolAddress((void**)&cl,    g_cl);
    cudaGetSymbolAddress((void**)&hh,    g_hh);
    cudaGetSymbolAddress((void**)&hl,    g_hl);
    cudaGetSymbolAddress((void**)&vh,    g_vh);
    cudaGetSymbolAddress((void**)&vl,    g_vl);

    static bool attr_set = false;
    if (!attr_set) {
        cudaFuncSetAttribute(attn_tile_kernel, cudaFuncAttributeMaxDynamicSharedMemorySize, ATT_SMEM);
        cudaFuncSetAttribute(gemm_bf16<0>, cudaFuncAttributeMaxDynamicSharedMemorySize, GT2_SMEM);
        cudaFuncSetAttribute(gemm_bf16<2>, cudaFuncAttributeMaxDynamicSharedMemorySize, GT2_SMEM);
        attr_set = true;
    }

    const size_t o_wv = 0;
    const size_t LSTRIDE = 4 * (size_t)D_ * D_ + 2 * (size_t)D_ * FF_;
    const size_t o_l0 = o_wv + (size_t)D_ * FD_;
    auto o_wq = [&](int i) { return o_l0 + i * LSTRIDE + 0 * (size_t)D_ * D_; };
    auto o_wk = [&](int i) { return o_l0 + i * LSTRIDE + 1 * (size_t)D_ * D_; };
    auto o_wa = [&](int i) { return o_l0 + i * LSTRIDE + 2 * (size_t)D_ * D_; };
    auto o_wo = [&](int i) { return o_l0 + i * LSTRIDE + 3 * (size_t)D_ * D_; };
    auto o_w1 = [&](int i) { return o_l0 + i * LSTRIDE + 4 * (size_t)D_ * D_; };
    auto o_w2 = [&](int i) { return o_l0 + i * LSTRIDE + 4 * (size_t)D_ * D_ + (size_t)FF_ * D_; };

    split_w_kernel<<<dim3(D_ / 32, FD_ / 32), dim3(32, 8)>>>(Wv, FD_, D_, wh + o_wv, wl + o_wv);
    for (int i = 0; i < 2; ++i) {
        split_w_kernel<<<dim3(D_ / 32, D_ / 32), dim3(32, 8)>>>(Wq + (size_t)i * D_ * D_, D_, D_, wh + o_wq(i), wl + o_wq(i));
        split_w_kernel<<<dim3(D_ / 32, D_ / 32), dim3(32, 8)>>>(Wk + (size_t)i * D_ * D_, D_, D_, wh + o_wk(i), wl + o_wk(i));
        split_w_kernel<<<dim3(D_ / 32, D_ / 32), dim3(32, 8)>>>(Wva + (size_t)i * D_ * D_, D_, D_, wh + o_wa(i), wl + o_wa(i));
        split_w_kernel<<<dim3(D_ / 32, D_ / 32), dim3(32, 8)>>>(Wo + (size_t)i * D_ * D_, D_, D_, wh + o_wo(i), wl + o_wo(i));
        split_w_kernel<<<dim3(FF_ / 32, D_ / 32), dim3(32, 8)>>>(W1 + (size_t)i * D_ * FF_, D_, FF_, wh + o_w1(i), wl + o_w1(i));
        split_w_kernel<<<dim3(D_ / 32, FF_ / 32), dim3(32, 8)>>>(W2 + (size_t)i * FF_ * D_, FF_, D_, wh + o_w2(i), wl + o_w2(i));
        concat_bias_kernel<<<6, 256>>>(bq + i * D_, bk + i * D_, bva + i * D_, bqkv + i * LDQKV);
    }

    // video split + projection
    split_a_kernel<<<(BT_ * FD_) / 1024, 256>>>(video, vh, vl);
    gemm_bf16<0><<<dim3(D_ / 128, BT_ / 128), 256, GT2_SMEM>>>(vh, vl, wh + o_wv, wl + o_wv, bv,
                                                               vproj, nullptr, nullptr, BT_, D_, FD_, 1.0f, 0);
    build_x_kernel<<<BS_, 128>>>(question, vproj, pos_emb, mod_emb, nv_g, nv_b, emb_g, emb_b, x, xh, xl);

    const float scale = 0.125f;
    for (int i = 0; i < 2; ++i) {
        // fused QKV: W rows [0,512)=Wq, [512,1024)=Wk, [1024,1536)=Wva (contiguous in split layout)
        gemm_bf16<0><<<dim3(LDQKV / 128, BS_ / 128), 256, GT2_SMEM>>>(xh, xl, wh + o_wq(i), wl + o_wq(i),
                                                                      bqkv + i * LDQKV, qkv, nullptr, nullptr,
                                                                      BS_, LDQKV, D_, scale, 512);

        attn_tile_kernel<<<dim3(B_ * H_, S_ / 64), 256, ATT_SMEM>>>(qkv, mask, ch, cl);

        gemm_bf16<0><<<dim3(D_ / 128, BS_ / 128), 256, GT2_SMEM>>>(ch, cl, wh + o_wo(i), wl + o_wo(i), bo + i * D_,
                                                                   yb, nullptr, nullptr, BS_, D_, D_, 1.0f, 0);
        add_ln_kernel<<<BS_, 128>>>(yb, x, x, xh, xl, ln1_g + i * D_, ln1_b + i * D_);

        gemm_bf16<2><<<dim3(FF_ / 128, BS_ / 128), 256, GT2_SMEM>>>(xh, xl, wh + o_w1(i), wl + o_w1(i), b1 + i * FF_,
                                                                    nullptr, hh, hl, BS_, FF_, D_, 1.0f, 0);
        gemm_bf16<0><<<dim3(D_ / 128, BS_ / 128), 256, GT2_SMEM>>>(hh, hl, wh + o_w2(i), wl + o_w2(i), b2 + i * D_,
                                                                   yb, nullptr, nullptr, BS_, D_, FF_, 1.0f, 0);

        float* dst = (i == 1) ? out : x;
        add_ln_kernel<<<BS_, 128>>>(yb, x, dst, xh, xl, ln2_g + i * D_, ln2_b + i * D_);
    }
    (void)in_sizes; (void)n_in; (void)out_size;
}

// round 9
// speedup vs baseline: 1.0944x; 1.0944x over previous
#include <cuda_runtime.h>
#include <cuda_bf16.h>
#include <math.h>
#include <stdint.h>

#define B_   64
#define Q_   64
#define T_   448
#define D_   512
#define FD_  1024
#define H_   8
#define DH_  64
#define FF_  2048
#define S_   512
#define BS_  (B_ * S_)   // 32768
#define BT_  (B_ * T_)   // 28672
#define LDQKV 1536

// ---------------- scratch (static device globals; no allocation) ----------------
__device__ float g_x[BS_ * D_];
__device__ float g_qkv[(size_t)BS_ * LDQKV];
__device__ float g_y[BS_ * D_];
__device__ float g_vproj[(size_t)BT_ * D_];
__device__ float g_bqkv[2 * LDQKV];

// bf16 hi/lo split activations
__device__ __nv_bfloat16 g_xh[BS_ * D_], g_xl[BS_ * D_];
__device__ __nv_bfloat16 g_ch[BS_ * D_], g_cl[BS_ * D_];
__device__ __nv_bfloat16 g_hh[(size_t)BS_ * FF_], g_hl[(size_t)BS_ * FF_];
__device__ __nv_bfloat16 g_vh[(size_t)BT_ * FD_], g_vl[(size_t)BT_ * FD_];

// split/transposed weights: hi + lo bf16, layout [N][K]
#define WSPLIT_TOTAL 6815744
__device__ __nv_bfloat16 g_wh[WSPLIT_TOTAL];
__device__ __nv_bfloat16 g_wl[WSPLIT_TOTAL];

// ---------------- small helpers ----------------
__device__ __forceinline__ float4 ld4(const float* p) { return *(const float4*)p; }
__device__ __forceinline__ void st4(float* p, float4 v) { *(float4*)p = v; }

__device__ __forceinline__ void split_store4(__nv_bfloat16* __restrict__ hp,
                                             __nv_bfloat16* __restrict__ lp,
                                             size_t off, float4 v) {
    __nv_bfloat16 h0 = __float2bfloat16(v.x);
    __nv_bfloat16 h1 = __float2bfloat16(v.y);
    __nv_bfloat16 h2 = __float2bfloat16(v.z);
    __nv_bfloat16 h3 = __float2bfloat16(v.w);
    __nv_bfloat16 l0 = __float2bfloat16(v.x - __bfloat162float(h0));
    __nv_bfloat16 l1 = __float2bfloat16(v.y - __bfloat162float(h1));
    __nv_bfloat16 l2 = __float2bfloat16(v.z - __bfloat162float(h2));
    __nv_bfloat16 l3 = __float2bfloat16(v.w - __bfloat162float(h3));
    *(__nv_bfloat162*)(hp + off)     = __nv_bfloat162(h0, h1);
    *(__nv_bfloat162*)(hp + off + 2) = __nv_bfloat162(h2, h3);
    *(__nv_bfloat162*)(lp + off)     = __nv_bfloat162(l0, l1);
    *(__nv_bfloat162*)(lp + off + 2) = __nv_bfloat162(l2, l3);
}

__device__ __forceinline__ float block_sum(float v, float* sm) {
#pragma unroll
    for (int o = 16; o; o >>= 1) v += __shfl_xor_sync(0xffffffffu, v, o);
    int w = threadIdx.x >> 5;
    __syncthreads();
    if ((threadIdx.x & 31) == 0) sm[w] = v;
    __syncthreads();
    return (sm[0] + sm[1]) + (sm[2] + sm[3]);
}

__device__ __forceinline__ void block_ln(float4& v, int i0,
                                         const float* __restrict__ g,
                                         const float* __restrict__ b,
                                         float* sm) {
    float s = v.x + v.y + v.z + v.w;
    s = block_sum(s, sm);
    float mean = s * (1.0f / (float)D_);
    float dx = v.x - mean, dy = v.y - mean, dz = v.z - mean, dw = v.w - mean;
    float ss = dx * dx + dy * dy + dz * dz + dw * dw;
    ss = block_sum(ss, sm);
    float inv = rsqrtf(ss * (1.0f / (float)D_) + 1e-12f);
    float4 gg = ld4(g + i0), bb = ld4(b + i0);
    v.x = dx * inv * gg.x + bb.x;
    v.y = dy * inv * gg.y + bb.y;
    v.z = dz * inv * gg.z + bb.z;
    v.w = dw * inv * gg.w + bb.w;
}

// ---------------- weight transpose+split: T[n][k] = W[k][n] as bf16 hi/lo ----------------
__global__ void split_w_kernel(const float* __restrict__ W, int K, int N,
                               __nv_bfloat16* __restrict__ Th, __nv_bfloat16* __restrict__ Tl) {
    __shared__ float tile[32][33];
    int k0 = blockIdx.y * 32, n0 = blockIdx.x * 32;
    int tx = threadIdx.x, ty = threadIdx.y;
    for (int j = ty; j < 32; j += 8)
        tile[j][tx] = W[(size_t)(k0 + j) * N + n0 + tx];
    __syncthreads();
    for (int j = ty; j < 32; j += 8) {
        float v = tile[tx][j];
        __nv_bfloat16 hi = __float2bfloat16(v);
        __nv_bfloat16 lo = __float2bfloat16(v - __bfloat162float(hi));
        size_t o = (size_t)(n0 + j) * K + k0 + tx;
        Th[o] = hi; Tl[o] = lo;
    }
}

// ---------------- plain elementwise split (video) ----------------
__global__ void split_a_kernel(const float* __restrict__ A,
                               __nv_bfloat16* __restrict__ Ah, __nv_bfloat16* __restrict__ Al) {
    size_t i = ((size_t)blockIdx.x * 256 + threadIdx.x) * 4;
    float4 v = ld4(A + i);
    split_store4(Ah, Al, i, v);
}

// ---------------- concat qkv bias ----------------
__global__ void concat_bias_kernel(const float* __restrict__ bq, const float* __restrict__ bk,
                                   const float* __restrict__ bv, float* __restrict__ dst) {
    int i = blockIdx.x * 256 + threadIdx.x;
    if (i < LDQKV)
        dst[i] = (i < 512) ? bq[i] : ((i < 1024) ? bk[i - 512] : bv[i - 1024]);
}

// ---------------- mma.sync GEMM: presplit bf16, 2-stage cp.async, occ 2 ----------------
// C = epilogue(A @ W^T + bias); A presplit [M][K] hi/lo, W presplit [N][K] hi/lo
// MODE 0: f32 out, cols < scale_cols multiplied by scale
// MODE 2: gelu -> bf16 hi/lo split out
#define GLDA 40
#define ARR  (128 * GLDA)
#define BUFE (4 * ARR)
#define GT2_SMEM (2 * BUFE * 2)   // 81920 bytes, 2 CTAs/SM

__device__ __forceinline__ void mma16816(float* d, const unsigned* a, const unsigned* b) {
    asm volatile(
        "mma.sync.aligned.m16n8k16.row.col.f32.bf16.bf16.f32 "
        "{%0,%1,%2,%3}, {%4,%5,%6,%7}, {%8,%9}, {%0,%1,%2,%3};\n"
        : "+f"(d[0]), "+f"(d[1]), "+f"(d[2]), "+f"(d[3])
        : "r"(a[0]), "r"(a[1]), "r"(a[2]), "r"(a[3]), "r"(b[0]), "r"(b[1]));
}
__device__ __forceinline__ void ldsm4(unsigned* r, unsigned addr) {
    asm volatile("ldmatrix.sync.aligned.m8n8.x4.shared.b16 {%0,%1,%2,%3}, [%4];\n"
                 : "=r"(r[0]), "=r"(r[1]), "=r"(r[2]), "=r"(r[3]) : "r"(addr));
}
__device__ __forceinline__ void ldsm2(unsigned* r, unsigned addr) {
    asm volatile("ldmatrix.sync.aligned.m8n8.x2.shared.b16 {%0,%1}, [%2];\n"
                 : "=r"(r[0]), "=r"(r[1]) : "r"(addr));
}
__device__ __forceinline__ void cpasync16(uint32_t dst, const void* src) {
    asm volatile("cp.async.cg.shared.global [%0], [%1], 16;" :: "r"(dst), "l"(src));
}
#define CP_COMMIT() asm volatile("cp.async.commit_group;" ::: "memory")
#define CP_WAIT1()  asm volatile("cp.async.wait_group 1;" ::: "memory")
#define CP_WAIT0()  asm volatile("cp.async.wait_group 0;" ::: "memory")

template<int MODE>
__global__ __launch_bounds__(256, 2)
void gemm_bf16(const __nv_bfloat16* __restrict__ Ah_g, const __nv_bfloat16* __restrict__ Al_g,
               const __nv_bfloat16* __restrict__ Wh_g, const __nv_bfloat16* __restrict__ Wl_g,
               const float* __restrict__ bias,
               float* __restrict__ C,
               __nv_bfloat16* __restrict__ Ch, __nv_bfloat16* __restrict__ Cl,
               int M, int N, int K, float scale, int scale_cols) {
    extern __shared__ __nv_bfloat16 smg[];

    int tid = threadIdx.x;
    int lane = tid & 31, wid = tid >> 5;
    int warpM = wid & 1, warpN = wid >> 1;
    int m0 = warpM * 64, n0 = warpN * 32;

    int blockM = blockIdx.y * 128;
    int blockN = blockIdx.x * 128;

    int a_row = lane & 15, a_cs = (lane >> 4) * 8;
    int b_row = lane & 7,  b_cs = ((lane >> 3) & 1) * 8;

    float acc[4][4][4];
#pragma unroll
    for (int f = 0; f < 4; ++f)
#pragma unroll
        for (int g = 0; g < 4; ++g)
#pragma unroll
            for (int j = 0; j < 4; ++j) acc[f][g][j] = 0.0f;

    int sr[2], sc[2];
#pragma unroll
    for (int wv = 0; wv < 2; ++wv) {
        int idx = tid + wv * 256;
        sr[wv] = idx >> 2;
        sc[wv] = (idx & 3) * 8;
    }

    auto stage = [&](int kt, int buf) {
        __nv_bfloat16* base = smg + buf * BUFE;
#pragma unroll
        for (int wv = 0; wv < 2; ++wv) {
            int r = sr[wv], c8 = sc[wv];
            uint32_t dsm = (uint32_t)__cvta_generic_to_shared(base + r * GLDA + c8);
            size_t ga = (size_t)(blockM + r) * K + kt * 32 + c8;
            size_t gb = (size_t)(blockN + r) * K + kt * 32 + c8;
            cpasync16(dsm,               Ah_g + ga);
            cpasync16(dsm + ARR * 2,     Al_g + ga);
            cpasync16(dsm + 2 * ARR * 2, Wh_g + gb);
            cpasync16(dsm + 3 * ARR * 2, Wl_g + gb);
        }
        CP_COMMIT();
    };

    int T = K >> 5;
    stage(0, 0);

    for (int kt = 0; kt < T; ++kt) {
        int buf = kt & 1;
        if (kt + 1 < T) { stage(kt + 1, buf ^ 1); CP_WAIT1(); }
        else            { CP_WAIT0(); }
        __syncthreads();

        __nv_bfloat16* Ahs = smg + buf * BUFE;
        __nv_bfloat16* Als = Ahs + ARR;
        __nv_bfloat16* Bhs = Ahs + 2 * ARR;
        __nv_bfloat16* Bls = Ahs + 3 * ARR;

#pragma unroll
        for (int kc = 0; kc < 32; kc += 16) {
            unsigned aF[16], bHf[8], bLf[8];
#pragma unroll
            for (int f = 0; f < 4; ++f)
                ldsm4(aF + 4 * f, (unsigned)__cvta_generic_to_shared(
                    Ahs + (m0 + f * 16 + a_row) * GLDA + kc + a_cs));
#pragma unroll
            for (int g = 0; g < 4; ++g)
                ldsm2(bHf + 2 * g, (unsigned)__cvta_generic_to_shared(
                    Bhs + (n0 + g * 8 + b_row) * GLDA + kc + b_cs));
#pragma unroll
            for (int g = 0; g < 4; ++g)
                ldsm2(bLf + 2 * g, (unsigned)__cvta_generic_to_shared(
                    Bls + (n0 + g * 8 + b_row) * GLDA + kc + b_cs));
#pragma unroll
            for (int f = 0; f < 4; ++f)
#pragma unroll
                for (int g = 0; g < 4; ++g)
                    mma16816(acc[f][g], aF + 4 * f, bHf + 2 * g);
#pragma unroll
            for (int f = 0; f < 4; ++f)
#pragma unroll
                for (int g = 0; g < 4; ++g)
                    mma16816(acc[f][g], aF + 4 * f, bLf + 2 * g);
#pragma unroll
            for (int f = 0; f < 4; ++f)
                ldsm4(aF + 4 * f, (unsigned)__cvta_generic_to_shared(
                    Als + (m0 + f * 16 + a_row) * GLDA + kc + a_cs));
#pragma unroll
            for (int f = 0; f < 4; ++f)
#pragma unroll
                for (int g = 0; g < 4; ++g)
                    mma16816(acc[f][g], aF + 4 * f, bHf + 2 * g);
        }
        __syncthreads();
    }

    // ---- epilogue ----
    bool do_scale = (MODE == 0) && (blockN < scale_cols);
#pragma unroll
    for (int f = 0; f < 4; ++f) {
#pragma unroll
        for (int g = 0; g < 4; ++g) {
            int col = blockN + n0 + g * 8 + (lane & 3) * 2;
            float b0 = bias[col], b1 = bias[col + 1];
#pragma unroll
            for (int half = 0; half < 2; ++half) {
                int row = blockM + m0 + f * 16 + (lane >> 2) + half * 8;
                float v0 = acc[f][g][half * 2 + 0] + b0;
                float v1 = acc[f][g][half * 2 + 1] + b1;
                if (MODE == 0) {
                    if (do_scale) { v0 *= scale; v1 *= scale; }
                    *(float2*)&C[(size_t)row * N + col] = make_float2(v0, v1);
                } else {
                    v0 = 0.5f * v0 * (1.0f + erff(v0 * 0.70710678118654752f));
                    v1 = 0.5f * v1 * (1.0f + erff(v1 * 0.70710678118654752f));
                    __nv_bfloat16 h0 = __float2bfloat16(v0);
                    __nv_bfloat16 h1 = __float2bfloat16(v1);
                    __nv_bfloat16 l0 = __float2bfloat16(v0 - __bfloat162float(h0));
                    __nv_bfloat16 l1 = __float2bfloat16(v1 - __bfloat162float(h1));
                    size_t off = (size_t)row * N + col;
                    *(__nv_bfloat162*)(Ch + off) = __nv_bfloat162(h0, h1);
                    *(__nv_bfloat162*)(Cl + off) = __nv_bfloat162(l0, l1);
                }
            }
        }
    }
}

// ---------------- build x ----------------
__global__ void build_x_kernel(const float* __restrict__ question,
                               const float* __restrict__ vproj,
                               const float* __restrict__ pos_emb,
                               const float* __restrict__ mod_emb,
                               const float* __restrict__ nv_g, const float* __restrict__ nv_b,
                               const float* __restrict__ emb_g, const float* __restrict__ emb_b,
                               float* __restrict__ x,
                               __nv_bfloat16* __restrict__ xh, __nv_bfloat16* __restrict__ xl) {
    __shared__ float sm[4];
    int row = blockIdx.x;
    int b = row / S_, s = row % S_;
    int i0 = threadIdx.x * 4;
    float4 v;
    if (s < Q_) {
        v = ld4(question + ((size_t)b * Q_ + s) * D_ + i0);
    } else {
        v = ld4(vproj + ((size_t)b * T_ + (s - Q_)) * D_ + i0);
        block_ln(v, i0, nv_g, nv_b, sm);
    }
    float4 pe = ld4(pos_emb + (size_t)s * D_ + i0);
    const float* me_p = mod_emb + (size_t)(s < Q_ ? 0 : 1) * D_ + i0;
    float4 me = ld4(me_p);
    v.x += pe.x + me.x; v.y += pe.y + me.y; v.z += pe.z + me.z; v.w += pe.w + me.w;
    block_ln(v, i0, emb_g, emb_b, sm);
    size_t off = (size_t)row * D_ + i0;
    st4(x + off, v);
    split_store4(xh, xl, off, v);
}

// ---------------- residual + LN ----------------
__global__ void add_ln_kernel(const float* __restrict__ y, const float* __restrict__ res,
                              float* __restrict__ out,
                              __nv_bfloat16* __restrict__ oh, __nv_bfloat16* __restrict__ ol,
                              const float* __restrict__ g, const float* __restrict__ bta) {
    __shared__ float sm[4];
    int row = blockIdx.x;
    int i0 = threadIdx.x * 4;
    size_t off = (size_t)row * D_ + i0;
    float4 a = ld4(y + off), r = ld4(res + off);
    float4 v = make_float4(a.x + r.x, a.y + r.y, a.z + r.z, a.w + r.w);
    block_ln(v, i0, g, bta, sm);
    st4(out + off, v);
    split_store4(oh, ol, off, v);
}

// ---------------- tiled flash attention (reads fused qkv, stride LDQKV) ----------------
__device__ __forceinline__ float4* tsl(float4* base, int r, int c4) {
    return base + r * 16 + ((c4 + (r >> 2)) & 15);
}

__global__ __launch_bounds__(256)
void attn_tile_kernel(const float* __restrict__ qkv, const int* __restrict__ mask,
                      __nv_bfloat16* __restrict__ ch, __nv_bfloat16* __restrict__ cl) {
    extern __shared__ float smdyn[];
    float4* Qs = (float4*)smdyn;
    float4* KP = Qs + 1024;
    float4* Vs = KP + 1024;
    __shared__ int ms[64];

    int bh = blockIdx.x;
    int b = bh >> 3, h = bh & 7;
    int q0 = blockIdx.y * 64;
    int tid = threadIdx.x;
    int tx = tid & 15, ty = tid >> 4;

    const float* qb = qkv + (size_t)b * S_ * LDQKV + h * DH_;
    const float* kb = qb + 512;
    const float* vb = qb + 1024;

    {
        int r = tid >> 2, c4 = (tid & 3) * 4;
        const float* src = qb + (size_t)(q0 + r) * LDQKV + c4 * 4;
#pragma unroll
        for (int u = 0; u < 4; ++u)
            *tsl(Qs, r, c4 + u) = ld4(src + u * 4);
    }

    float m[4], l[4], o[4][4];
#pragma unroll
    for (int i = 0; i < 4; ++i) {
        m[i] = -INFINITY; l[i] = 0.0f;
#pragma unroll
        for (int c = 0; c < 4; ++c) o[i][c] = 0.0f;
    }

    for (int kt = 0; kt < 8; ++kt) {
        int k0 = kt * 64;
        __syncthreads();
        {
            int r = tid >> 2, c4 = (tid & 3) * 4;
            const float* ks = kb + (size_t)(k0 + r) * LDQKV + c4 * 4;
            const float* vs = vb + (size_t)(k0 + r) * LDQKV + c4 * 4;
#pragma unroll
            for (int u = 0; u < 4; ++u) {
                *tsl(KP, r, c4 + u) = ld4(ks + u * 4);
                *tsl(Vs, r, c4 + u) = ld4(vs + u * 4);
            }
            if (tid < 64) ms[tid] = mask[b * S_ + k0 + tid];
        }
        __syncthreads();

        float s[4][4];
#pragma unroll
        for (int i = 0; i < 4; ++i)
#pragma unroll
            for (int j = 0; j < 4; ++j) s[i][j] = 0.0f;

        for (int d4 = 0; d4 < 16; ++d4) {
            float4 qv[4], kv[4];
#pragma unroll
            for (int i = 0; i < 4; ++i) qv[i] = *tsl(Qs, ty * 4 + i, d4);
#pragma unroll
            for (int j = 0; j < 4; ++j) kv[j] = *tsl(KP, tx * 4 + j, d4);
#pragma unroll
            for (int i = 0; i < 4; ++i)
#pragma unroll
                for (int j = 0; j < 4; ++j) {
                    s[i][j] = fmaf(qv[i].x, kv[j].x, s[i][j]);
                    s[i][j] = fmaf(qv[i].y, kv[j].y, s[i][j]);
                    s[i][j] = fmaf(qv[i].z, kv[j].z, s[i][j]);
                    s[i][j] = fmaf(qv[i].w, kv[j].w, s[i][j]);
                }
        }
#pragma unroll
        for (int j = 0; j < 4; ++j) {
            if (ms[tx * 4 + j] == 0) {
#pragma unroll
                for (int i = 0; i < 4; ++i) s[i][j] = -INFINITY;
            }
        }

        float p[4][4], corr[4], psum[4];
#pragma unroll
        for (int i = 0; i < 4; ++i) {
            float rm = fmaxf(fmaxf(s[i][0], s[i][1]), fmaxf(s[i][2], s[i][3]));
#pragma unroll
            for (int off = 1; off < 16; off <<= 1)
                rm = fmaxf(rm, __shfl_xor_sync(0xffffffffu, rm, off));
            float nm = fmaxf(m[i], rm);
            if (nm == -INFINITY) {
                corr[i] = 1.0f;
#pragma unroll
                for (int j = 0; j < 4; ++j) p[i][j] = 0.0f;
            } else {
                corr[i] = __expf(m[i] - nm);
#pragma unroll
                for (int j = 0; j < 4; ++j) p[i][j] = __expf(s[i][j] - nm);
                m[i] = nm;
            }
            float ps = (p[i][0] + p[i][1]) + (p[i][2] + p[i][3]);
#pragma unroll
            for (int off = 1; off < 16; off <<= 1)
                ps += __shfl_xor_sync(0xffffffffu, ps, off);
            psum[i] = ps;
        }

        __syncthreads();
#pragma unroll
        for (int i = 0; i < 4; ++i) {
            int r = ty * 4 + i;
            float* dst = (float*)(KP + r * 16 + ((tx + (r >> 2)) & 15));
#pragma unroll
            for (int j = 0; j < 4; ++j) dst[j] = p[i][j];
        }
#pragma unroll
        for (int i = 0; i < 4; ++i) {
            l[i] = l[i] * corr[i] + psum[i];
#pragma unroll
            for (int c = 0; c < 4; ++c) o[i][c] *= corr[i];
        }
        __syncthreads();

        for (int kk4 = 0; kk4 < 16; ++kk4) {
            float4 pv[4], vv[4];
#pragma unroll
            for (int i = 0; i < 4; ++i) pv[i] = *tsl(KP, ty * 4 + i, kk4);
#pragma unroll
            for (int u = 0; u < 4; ++u) vv[u] = *tsl(Vs, kk4 * 4 + u, tx);
#pragma unroll
            for (int i = 0; i < 4; ++i) {
                o[i][0] = fmaf(pv[i].x, vv[0].x, o[i][0]);
                o[i][1] = fmaf(pv[i].x, vv[0].y, o[i][1]);
                o[i][2] = fmaf(pv[i].x, vv[0].z, o[i][2]);
                o[i][3] = fmaf(pv[i].x, vv[0].w, o[i][3]);
                o[i][0] = fmaf(pv[i].y, vv[1].x, o[i][0]);
                o[i][1] = fmaf(pv[i].y, vv[1].y, o[i][1]);
                o[i][2] = fmaf(pv[i].y, vv[1].z, o[i][2]);
                o[i][3] = fmaf(pv[i].y, vv[1].w, o[i][3]);
                o[i][0] = fmaf(pv[i].z, vv[2].x, o[i][0]);
                o[i][1] = fmaf(pv[i].z, vv[2].y, o[i][1]);
                o[i][2] = fmaf(pv[i].z, vv[2].z, o[i][2]);
                o[i][3] = fmaf(pv[i].z, vv[2].w, o[i][3]);
                o[i][0] = fmaf(pv[i].w, vv[3].x, o[i][0]);
                o[i][1] = fmaf(pv[i].w, vv[3].y, o[i][1]);
                o[i][2] = fmaf(pv[i].w, vv[3].z, o[i][2]);
                o[i][3] = fmaf(pv[i].w, vv[3].w, o[i][3]);
            }
        }
    }

#pragma unroll
    for (int i = 0; i < 4; ++i) {
        float inv = (l[i] > 0.0f) ? (1.0f / l[i]) : 0.0f;
        float4 r = make_float4(o[i][0] * inv, o[i][1] * inv, o[i][2] * inv, o[i][3] * inv);
        size_t off = (size_t)(b * S_ + q0 + ty * 4 + i) * D_ + h * DH_ + tx * 4;
        split_store4(ch, cl, off, r);
    }
}

#define ATT_SMEM (3 * 64 * 16 * 16)   // 49152 bytes

// ---------------- launcher ----------------
extern "C" void kernel_launch(void* const* d_in, const int* in_sizes, int n_in,
                              void* d_out, int out_size) {
    const float* video    = (const float*)d_in[0];
    const float* question = (const float*)d_in[1];
    const int*   mask     = (const int*)d_in[2];
    const float* pos_emb  = (const float*)d_in[3];
    const float* mod_emb  = (const float*)d_in[4];
    const float* Wv   = (const float*)d_in[5];
    const float* bv   = (const float*)d_in[6];
    const float* nv_g = (const float*)d_in[7];
    const float* nv_b = (const float*)d_in[8];
    const float* emb_g = (const float*)d_in[9];
    const float* emb_b = (const float*)d_in[10];
    const float* Wq  = (const float*)d_in[11];
    const float* bq  = (const float*)d_in[12];
    const float* Wk  = (const float*)d_in[13];
    const float* bk  = (const float*)d_in[14];
    const float* Wva = (const float*)d_in[15];
    const float* bva = (const float*)d_in[16];
    const float* Wo  = (const float*)d_in[17];
    const float* bo  = (const float*)d_in[18];
    const float* ln1_g = (const float*)d_in[19];
    const float* ln1_b = (const float*)d_in[20];
    const float* W1  = (const float*)d_in[21];
    const float* b1  = (const float*)d_in[22];
    const float* W2  = (const float*)d_in[23];
    const float* b2  = (const float*)d_in[24];
    const float* ln2_g = (const float*)d_in[25];
    const float* ln2_b = (const float*)d_in[26];
    float* out = (float*)d_out;

    float *x, *qkv, *yb, *vproj, *bqkv;
    __nv_bfloat16 *wh, *wl, *xh, *xl, *ch, *cl, *hh, *hl, *vh, *vl;
    cudaGetSymbolAddress((void**)&x,     g_x);
    cudaGetSymbolAddress((void**)&qkv,   g_qkv);
    cudaGetSymbolAddress((void**)&yb,    g_y);
    cudaGetSymbolAddress((void**)&vproj, g_vproj);
    cudaGetSymbolAddress((void**)&bqkv,  g_bqkv);
    cudaGetSymbolAddress((void**)&wh,    g_wh);
    cudaGetSymbolAddress((void**)&wl,    g_wl);
    cudaGetSymbolAddress((void**)&xh,    g_xh);
    cudaGetSymbolAddress((void**)&xl,    g_xl);
    cudaGetSymbolAddress((void**)&ch,    g_ch);
    cudaGetSymbolAddress((void**)&cl,    g_cl);
    cudaGetSymbolAddress((void**)&hh,    g_hh);
    cudaGetSymbolAddress((void**)&hl,    g_hl);
    cudaGetSymbolAddress((void**)&vh,    g_vh);
    cudaGetSymbolAddress((void**)&vl,    g_vl);

    static bool attr_set = false;
    if (!attr_set) {
        cudaFuncSetAttribute(attn_tile_kernel, cudaFuncAttributeMaxDynamicSharedMemorySize, ATT_SMEM);
        cudaFuncSetAttribute(gemm_bf16<0>, cudaFuncAttributeMaxDynamicSharedMemorySize, GT2_SMEM);
        cudaFuncSetAttribute(gemm_bf16<2>, cudaFuncAttributeMaxDynamicSharedMemorySize, GT2_SMEM);
        attr_set = true;
    }

    const size_t o_wv = 0;
    const size_t LSTRIDE = 4 * (size_t)D_ * D_ + 2 * (size_t)D_ * FF_;
    const size_t o_l0 = o_wv + (size_t)D_ * FD_;
    auto o_wq = [&](int i) { return o_l0 + i * LSTRIDE + 0 * (size_t)D_ * D_; };
    auto o_wk = [&](int i) { return o_l0 + i * LSTRIDE + 1 * (size_t)D_ * D_; };
    auto o_wa = [&](int i) { return o_l0 + i * LSTRIDE + 2 * (size_t)D_ * D_; };
    auto o_wo = [&](int i) { return o_l0 + i * LSTRIDE + 3 * (size_t)D_ * D_; };
    auto o_w1 = [&](int i) { return o_l0 + i * LSTRIDE + 4 * (size_t)D_ * D_; };
    auto o_w2 = [&](int i) { return o_l0 + i * LSTRIDE + 4 * (size_t)D_ * D_ + (size_t)FF_ * D_; };

    split_w_kernel<<<dim3(D_ / 32, FD_ / 32), dim3(32, 8)>>>(Wv, FD_, D_, wh + o_wv, wl + o_wv);
    for (int i = 0; i < 2; ++i) {
        split_w_kernel<<<dim3(D_ / 32, D_ / 32), dim3(32, 8)>>>(Wq + (size_t)i * D_ * D_, D_, D_, wh + o_wq(i), wl + o_wq(i));
        split_w_kernel<<<dim3(D_ / 32, D_ / 32), dim3(32, 8)>>>(Wk + (size_t)i * D_ * D_, D_, D_, wh + o_wk(i), wl + o_wk(i));
        split_w_kernel<<<dim3(D_ / 32, D_ / 32), dim3(32, 8)>>>(Wva + (size_t)i * D_ * D_, D_, D_, wh + o_wa(i), wl + o_wa(i));
        split_w_kernel<<<dim3(D_ / 32, D_ / 32), dim3(32, 8)>>>(Wo + (size_t)i * D_ * D_, D_, D_, wh + o_wo(i), wl + o_wo(i));
        split_w_kernel<<<dim3(FF_ / 32, D_ / 32), dim3(32, 8)>>>(W1 + (size_t)i * D_ * FF_, D_, FF_, wh + o_w1(i), wl + o_w1(i));
        split_w_kernel<<<dim3(D_ / 32, FF_ / 32), dim3(32, 8)>>>(W2 + (size_t)i * FF_ * D_, FF_, D_, wh + o_w2(i), wl + o_w2(i));
        concat_bias_kernel<<<6, 256>>>(bq + i * D_, bk + i * D_, bva + i * D_, bqkv + i * LDQKV);
    }

    // video split + projection
    split_a_kernel<<<(BT_ * FD_) / 1024, 256>>>(video, vh, vl);
    gemm_bf16<0><<<dim3(D_ / 128, BT_ / 128), 256, GT2_SMEM>>>(vh, vl, wh + o_wv, wl + o_wv, bv,
                                                               vproj, nullptr, nullptr, BT_, D_, FD_, 1.0f, 0);
    build_x_kernel<<<BS_, 128>>>(question, vproj, pos_emb, mod_emb, nv_g, nv_b, emb_g, emb_b, x, xh, xl);

    const float scale = 0.125f;
    for (int i = 0; i < 2; ++i) {
        // fused QKV: W rows [0,512)=Wq, [512,1024)=Wk, [1024,1536)=Wva (contiguous in split layout)
        gemm_bf16<0><<<dim3(LDQKV / 128, BS_ / 128), 256, GT2_SMEM>>>(xh, xl, wh + o_wq(i), wl + o_wq(i),
                                                                      bqkv + i * LDQKV, qkv, nullptr, nullptr,
                                                                      BS_, LDQKV, D_, scale, 512);

        attn_tile_kernel<<<dim3(B_ * H_, S_ / 64), 256, ATT_SMEM>>>(qkv, mask, ch, cl);

        gemm_bf16<0><<<dim3(D_ / 128, BS_ / 128), 256, GT2_SMEM>>>(ch, cl, wh + o_wo(i), wl + o_wo(i), bo + i * D_,
                                                                   yb, nullptr, nullptr, BS_, D_, D_, 1.0f, 0);
        add_ln_kernel<<<BS_, 128>>>(yb, x, x, xh, xl, ln1_g + i * D_, ln1_b + i * D_);

        gemm_bf16<2><<<dim3(FF_ / 128, BS_ / 128), 256, GT2_SMEM>>>(xh, xl, wh + o_w1(i), wl + o_w1(i), b1 + i * FF_,
                                                                    nullptr, hh, hl, BS_, FF_, D_, 1.0f, 0);
        gemm_bf16<0><<<dim3(D_ / 128, BS_ / 128), 256, GT2_SMEM>>>(hh, hl, wh + o_w2(i), wl + o_w2(i), b2 + i * D_,
                                                                   yb, nullptr, nullptr, BS_, D_, FF_, 1.0f, 0);

        float* dst = (i == 1) ? out : x;
        add_ln_kernel<<<BS_, 128>>>(yb, x, dst, xh, xl, ln2_g + i * D_, ln2_b + i * D_);
    }
    (void)in_sizes; (void)n_in; (void)out_size;
}

// round 10
// speedup vs baseline: 1.2949x; 1.1832x over previous
#include <cuda_runtime.h>
#include <cuda_fp16.h>
#include <math.h>
#include <stdint.h>

#define B_   64
#define Q_   64
#define T_   448
#define D_   512
#define FD_  1024
#define H_   8
#define DH_  64
#define FF_  2048
#define S_   512
#define BS_  (B_ * S_)   // 32768
#define BT_  (B_ * T_)   // 28672
#define LDQKV 1536

// ---------------- scratch (static device globals; no allocation) ----------------
__device__ float g_x[BS_ * D_];
__device__ float g_qkv[(size_t)BS_ * LDQKV];
__device__ float g_y[BS_ * D_];
__device__ float g_vproj[(size_t)BT_ * D_];
__device__ float g_bqkv[2 * LDQKV];

// fp16 hi/lo split activations
__device__ __half g_xh[BS_ * D_], g_xl[BS_ * D_];
__device__ __half g_ch[BS_ * D_], g_cl[BS_ * D_];
__device__ __half g_hh[(size_t)BS_ * FF_], g_hl[(size_t)BS_ * FF_];
__device__ __half g_vh[(size_t)BT_ * FD_], g_vl[(size_t)BT_ * FD_];

// transposed weights: fp16 hi only, layout [N][K]
#define WSPLIT_TOTAL 6815744
__device__ __half g_wh[WSPLIT_TOTAL];

// ---------------- small helpers ----------------
__device__ __forceinline__ float4 ld4(const float* p) { return *(const float4*)p; }
__device__ __forceinline__ void st4(float* p, float4 v) { *(float4*)p = v; }

__device__ __forceinline__ void split_store4(__half* __restrict__ hp,
                                             __half* __restrict__ lp,
                                             size_t off, float4 v) {
    __half h0 = __float2half_rn(v.x);
    __half h1 = __float2half_rn(v.y);
    __half h2 = __float2half_rn(v.z);
    __half h3 = __float2half_rn(v.w);
    __half l0 = __float2half_rn(v.x - __half2float(h0));
    __half l1 = __float2half_rn(v.y - __half2float(h1));
    __half l2 = __float2half_rn(v.z - __half2float(h2));
    __half l3 = __float2half_rn(v.w - __half2float(h3));
    *(__half2*)(hp + off)     = __halves2half2(h0, h1);
    *(__half2*)(hp + off + 2) = __halves2half2(h2, h3);
    *(__half2*)(lp + off)     = __halves2half2(l0, l1);
    *(__half2*)(lp + off + 2) = __halves2half2(l2, l3);
}

__device__ __forceinline__ float block_sum(float v, float* sm) {
#pragma unroll
    for (int o = 16; o; o >>= 1) v += __shfl_xor_sync(0xffffffffu, v, o);
    int w = threadIdx.x >> 5;
    __syncthreads();
    if ((threadIdx.x & 31) == 0) sm[w] = v;
    __syncthreads();
    return (sm[0] + sm[1]) + (sm[2] + sm[3]);
}

__device__ __forceinline__ void block_ln(float4& v, int i0,
                                         const float* __restrict__ g,
                                         const float* __restrict__ b,
                                         float* sm) {
    float s = v.x + v.y + v.z + v.w;
    s = block_sum(s, sm);
    float mean = s * (1.0f / (float)D_);
    float dx = v.x - mean, dy = v.y - mean, dz = v.z - mean, dw = v.w - mean;
    float ss = dx * dx + dy * dy + dz * dz + dw * dw;
    ss = block_sum(ss, sm);
    float inv = rsqrtf(ss * (1.0f / (float)D_) + 1e-12f);
    float4 gg = ld4(g + i0), bb = ld4(b + i0);
    v.x = dx * inv * gg.x + bb.x;
    v.y = dy * inv * gg.y + bb.y;
    v.z = dz * inv * gg.z + bb.z;
    v.w = dw * inv * gg.w + bb.w;
}

// ---------------- weight transpose: T[n][k] = fp16(W[k][n]) ----------------
__global__ void split_w_kernel(const float* __restrict__ W, int K, int N,
                               __half* __restrict__ Th) {
    __shared__ float tile[32][33];
    int k0 = blockIdx.y * 32, n0 = blockIdx.x * 32;
    int tx = threadIdx.x, ty = threadIdx.y;
    for (int j = ty; j < 32; j += 8)
        tile[j][tx] = W[(size_t)(k0 + j) * N + n0 + tx];
    __syncthreads();
    for (int j = ty; j < 32; j += 8) {
        size_t o = (size_t)(n0 + j) * K + k0 + tx;
        Th[o] = __float2half_rn(tile[tx][j]);
    }
}

// ---------------- plain elementwise split (video) ----------------
__global__ void split_a_kernel(const float* __restrict__ A,
                               __half* __restrict__ Ah, __half* __restrict__ Al) {
    size_t i = ((size_t)blockIdx.x * 256 + threadIdx.x) * 4;
    float4 v = ld4(A + i);
    split_store4(Ah, Al, i, v);
}

// ---------------- concat qkv bias ----------------
__global__ void concat_bias_kernel(const float* __restrict__ bq, const float* __restrict__ bk,
                                   const float* __restrict__ bv, float* __restrict__ dst) {
    int i = blockIdx.x * 256 + threadIdx.x;
    if (i < LDQKV)
        dst[i] = (i < 512) ? bq[i] : ((i < 1024) ? bk[i - 512] : bv[i - 1024]);
}

// ---------------- mma.sync GEMM: fp16 2-pass, 2-stage cp.async, occ 2 ----------------
// C = epilogue(A @ W^T + bias); A presplit [M][K] fp16 hi/lo, W [N][K] fp16
// MODE 0: f32 out, cols < scale_cols multiplied by scale
// MODE 2: gelu -> fp16 hi/lo split out
#define GLDA 40
#define ARR  (128 * GLDA)
#define BUFE (3 * ARR)
#define GT2_SMEM (2 * BUFE * 2)   // 61440 bytes, 2 CTAs/SM

__device__ __forceinline__ void mma16816(float* d, const unsigned* a, const unsigned* b) {
    asm volatile(
        "mma.sync.aligned.m16n8k16.row.col.f32.f16.f16.f32 "
        "{%0,%1,%2,%3}, {%4,%5,%6,%7}, {%8,%9}, {%0,%1,%2,%3};\n"
        : "+f"(d[0]), "+f"(d[1]), "+f"(d[2]), "+f"(d[3])
        : "r"(a[0]), "r"(a[1]), "r"(a[2]), "r"(a[3]), "r"(b[0]), "r"(b[1]));
}
__device__ __forceinline__ void ldsm4(unsigned* r, unsigned addr) {
    asm volatile("ldmatrix.sync.aligned.m8n8.x4.shared.b16 {%0,%1,%2,%3}, [%4];\n"
                 : "=r"(r[0]), "=r"(r[1]), "=r"(r[2]), "=r"(r[3]) : "r"(addr));
}
__device__ __forceinline__ void ldsm2(unsigned* r, unsigned addr) {
    asm volatile("ldmatrix.sync.aligned.m8n8.x2.shared.b16 {%0,%1}, [%2];\n"
                 : "=r"(r[0]), "=r"(r[1]) : "r"(addr));
}
__device__ __forceinline__ void cpasync16(uint32_t dst, const void* src) {
    asm volatile("cp.async.cg.shared.global [%0], [%1], 16;" :: "r"(dst), "l"(src));
}
#define CP_COMMIT() asm volatile("cp.async.commit_group;" ::: "memory")
#define CP_WAIT1()  asm volatile("cp.async.wait_group 1;" ::: "memory")
#define CP_WAIT0()  asm volatile("cp.async.wait_group 0;" ::: "memory")

template<int MODE>
__global__ __launch_bounds__(256, 2)
void gemm_fp16(const __half* __restrict__ Ah_g, const __half* __restrict__ Al_g,
               const __half* __restrict__ Wh_g,
               const float* __restrict__ bias,
               float* __restrict__ C,
               __half* __restrict__ Ch, __half* __restrict__ Cl,
               int M, int N, int K, float scale, int scale_cols) {
    extern __shared__ __half smg[];

    int tid = threadIdx.x;
    int lane = tid & 31, wid = tid >> 5;
    int warpM = wid & 1, warpN = wid >> 1;
    int m0 = warpM * 64, n0 = warpN * 32;

    int blockM = blockIdx.y * 128;
    int blockN = blockIdx.x * 128;

    int a_row = lane & 15, a_cs = (lane >> 4) * 8;
    int b_row = lane & 7,  b_cs = ((lane >> 3) & 1) * 8;

    float acc[4][4][4];
#pragma unroll
    for (int f = 0; f < 4; ++f)
#pragma unroll
        for (int g = 0; g < 4; ++g)
#pragma unroll
            for (int j = 0; j < 4; ++j) acc[f][g][j] = 0.0f;

    int sr[2], sc[2];
#pragma unroll
    for (int wv = 0; wv < 2; ++wv) {
        int idx = tid + wv * 256;
        sr[wv] = idx >> 2;
        sc[wv] = (idx & 3) * 8;
    }

    auto stage = [&](int kt, int buf) {
        __half* base = smg + buf * BUFE;
#pragma unroll
        for (int wv = 0; wv < 2; ++wv) {
            int r = sr[wv], c8 = sc[wv];
            uint32_t dsm = (uint32_t)__cvta_generic_to_shared(base + r * GLDA + c8);
            size_t ga = (size_t)(blockM + r) * K + kt * 32 + c8;
            size_t gb = (size_t)(blockN + r) * K + kt * 32 + c8;
            cpasync16(dsm,               Ah_g + ga);
            cpasync16(dsm + ARR * 2,     Al_g + ga);
            cpasync16(dsm + 2 * ARR * 2, Wh_g + gb);
        }
        CP_COMMIT();
    };

    int T = K >> 5;
    stage(0, 0);

    for (int kt = 0; kt < T; ++kt) {
        int buf = kt & 1;
        if (kt + 1 < T) { stage(kt + 1, buf ^ 1); CP_WAIT1(); }
        else            { CP_WAIT0(); }
        __syncthreads();

        __half* Ahs = smg + buf * BUFE;
        __half* Als = Ahs + ARR;
        __half* Bhs = Ahs + 2 * ARR;

#pragma unroll
        for (int kc = 0; kc < 32; kc += 16) {
            unsigned aF[16], bHf[8];
#pragma unroll
            for (int f = 0; f < 4; ++f)
                ldsm4(aF + 4 * f, (unsigned)__cvta_generic_to_shared(
                    Ahs + (m0 + f * 16 + a_row) * GLDA + kc + a_cs));
#pragma unroll
            for (int g = 0; g < 4; ++g)
                ldsm2(bHf + 2 * g, (unsigned)__cvta_generic_to_shared(
                    Bhs + (n0 + g * 8 + b_row) * GLDA + kc + b_cs));
            // hi * W
#pragma unroll
            for (int f = 0; f < 4; ++f)
#pragma unroll
                for (int g = 0; g < 4; ++g)
                    mma16816(acc[f][g], aF + 4 * f, bHf + 2 * g);
            // lo * W
#pragma unroll
            for (int f = 0; f < 4; ++f)
                ldsm4(aF + 4 * f, (unsigned)__cvta_generic_to_shared(
                    Als + (m0 + f * 16 + a_row) * GLDA + kc + a_cs));
#pragma unroll
            for (int f = 0; f < 4; ++f)
#pragma unroll
                for (int g = 0; g < 4; ++g)
                    mma16816(acc[f][g], aF + 4 * f, bHf + 2 * g);
        }
        __syncthreads();
    }

    // ---- epilogue ----
    bool do_scale = (MODE == 0) && (blockN < scale_cols);
#pragma unroll
    for (int f = 0; f < 4; ++f) {
#pragma unroll
        for (int g = 0; g < 4; ++g) {
            int col = blockN + n0 + g * 8 + (lane & 3) * 2;
            float b0 = bias[col], b1 = bias[col + 1];
#pragma unroll
            for (int half_ = 0; half_ < 2; ++half_) {
                int row = blockM + m0 + f * 16 + (lane >> 2) + half_ * 8;
                float v0 = acc[f][g][half_ * 2 + 0] + b0;
                float v1 = acc[f][g][half_ * 2 + 1] + b1;
                if (MODE == 0) {
                    if (do_scale) { v0 *= scale; v1 *= scale; }
                    *(float2*)&C[(size_t)row * N + col] = make_float2(v0, v1);
                } else {
                    v0 = 0.5f * v0 * (1.0f + erff(v0 * 0.70710678118654752f));
                    v1 = 0.5f * v1 * (1.0f + erff(v1 * 0.70710678118654752f));
                    __half h0 = __float2half_rn(v0);
                    __half h1 = __float2half_rn(v1);
                    __half l0 = __float2half_rn(v0 - __half2float(h0));
                    __half l1 = __float2half_rn(v1 - __half2float(h1));
                    size_t off = (size_t)row * N + col;
                    *(__half2*)(Ch + off) = __halves2half2(h0, h1);
                    *(__half2*)(Cl + off) = __halves2half2(l0, l1);
                }
            }
        }
    }
}

// ---------------- build x ----------------
__global__ void build_x_kernel(const float* __restrict__ question,
                               const float* __restrict__ vproj,
                               const float* __restrict__ pos_emb,
                               const float* __restrict__ mod_emb,
                               const float* __restrict__ nv_g, const float* __restrict__ nv_b,
                               const float* __restrict__ emb_g, const float* __restrict__ emb_b,
                               float* __restrict__ x,
                               __half* __restrict__ xh, __half* __restrict__ xl) {
    __shared__ float sm[4];
    int row = blockIdx.x;
    int b = row / S_, s = row % S_;
    int i0 = threadIdx.x * 4;
    float4 v;
    if (s < Q_) {
        v = ld4(question + ((size_t)b * Q_ + s) * D_ + i0);
    } else {
        v = ld4(vproj + ((size_t)b * T_ + (s - Q_)) * D_ + i0);
        block_ln(v, i0, nv_g, nv_b, sm);
    }
    float4 pe = ld4(pos_emb + (size_t)s * D_ + i0);
    const float* me_p = mod_emb + (size_t)(s < Q_ ? 0 : 1) * D_ + i0;
    float4 me = ld4(me_p);
    v.x += pe.x + me.x; v.y += pe.y + me.y; v.z += pe.z + me.z; v.w += pe.w + me.w;
    block_ln(v, i0, emb_g, emb_b, sm);
    size_t off = (size_t)row * D_ + i0;
    st4(x + off, v);
    split_store4(xh, xl, off, v);
}

// ---------------- residual + LN ----------------
__global__ void add_ln_kernel(const float* __restrict__ y, const float* __restrict__ res,
                              float* __restrict__ out,
                              __half* __restrict__ oh, __half* __restrict__ ol,
                              const float* __restrict__ g, const float* __restrict__ bta) {
    __shared__ float sm[4];
    int row = blockIdx.x;
    int i0 = threadIdx.x * 4;
    size_t off = (size_t)row * D_ + i0;
    float4 a = ld4(y + off), r = ld4(res + off);
    float4 v = make_float4(a.x + r.x, a.y + r.y, a.z + r.z, a.w + r.w);
    block_ln(v, i0, g, bta, sm);
    st4(out + off, v);
    split_store4(oh, ol, off, v);
}

// ---------------- tiled flash attention (reads fused qkv, stride LDQKV) ----------------
__device__ __forceinline__ float4* tsl(float4* base, int r, int c4) {
    return base + r * 16 + ((c4 + (r >> 2)) & 15);
}

__global__ __launch_bounds__(256)
void attn_tile_kernel(const float* __restrict__ qkv, const int* __restrict__ mask,
                      __half* __restrict__ ch, __half* __restrict__ cl) {
    extern __shared__ float smdyn[];
    float4* Qs = (float4*)smdyn;
    float4* KP = Qs + 1024;
    float4* Vs = KP + 1024;
    __shared__ int ms[64];

    int bh = blockIdx.x;
    int b = bh >> 3, h = bh & 7;
    int q0 = blockIdx.y * 64;
    int tid = threadIdx.x;
    int tx = tid & 15, ty = tid >> 4;

    const float* qb = qkv + (size_t)b * S_ * LDQKV + h * DH_;
    const float* kb = qb + 512;
    const float* vb = qb + 1024;

    {
        int r = tid >> 2, c4 = (tid & 3) * 4;
        const float* src = qb + (size_t)(q0 + r) * LDQKV + c4 * 4;
#pragma unroll
        for (int u = 0; u < 4; ++u)
            *tsl(Qs, r, c4 + u) = ld4(src + u * 4);
    }

    float m[4], l[4], o[4][4];
#pragma unroll
    for (int i = 0; i < 4; ++i) {
        m[i] = -INFINITY; l[i] = 0.0f;
#pragma unroll
        for (int c = 0; c < 4; ++c) o[i][c] = 0.0f;
    }

    for (int kt = 0; kt < 8; ++kt) {
        int k0 = kt * 64;
        __syncthreads();
        {
            int r = tid >> 2, c4 = (tid & 3) * 4;
            const float* ks = kb + (size_t)(k0 + r) * LDQKV + c4 * 4;
            const float* vs = vb + (size_t)(k0 + r) * LDQKV + c4 * 4;
#pragma unroll
            for (int u = 0; u < 4; ++u) {
                *tsl(KP, r, c4 + u) = ld4(ks + u * 4);
                *tsl(Vs, r, c4 + u) = ld4(vs + u * 4);
            }
            if (tid < 64) ms[tid] = mask[b * S_ + k0 + tid];
        }
        __syncthreads();

        float s[4][4];
#pragma unroll
        for (int i = 0; i < 4; ++i)
#pragma unroll
            for (int j = 0; j < 4; ++j) s[i][j] = 0.0f;

        for (int d4 = 0; d4 < 16; ++d4) {
            float4 qv[4], kv[4];
#pragma unroll
            for (int i = 0; i < 4; ++i) qv[i] = *tsl(Qs, ty * 4 + i, d4);
#pragma unroll
            for (int j = 0; j < 4; ++j) kv[j] = *tsl(KP, tx * 4 + j, d4);
#pragma unroll
            for (int i = 0; i < 4; ++i)
#pragma unroll
                for (int j = 0; j < 4; ++j) {
                    s[i][j] = fmaf(qv[i].x, kv[j].x, s[i][j]);
                    s[i][j] = fmaf(qv[i].y, kv[j].y, s[i][j]);
                    s[i][j] = fmaf(qv[i].z, kv[j].z, s[i][j]);
                    s[i][j] = fmaf(qv[i].w, kv[j].w, s[i][j]);
                }
        }
#pragma unroll
        for (int j = 0; j < 4; ++j) {
            if (ms[tx * 4 + j] == 0) {
#pragma unroll
                for (int i = 0; i < 4; ++i) s[i][j] = -INFINITY;
            }
        }

        float p[4][4], corr[4], psum[4];
#pragma unroll
        for (int i = 0; i < 4; ++i) {
            float rm = fmaxf(fmaxf(s[i][0], s[i][1]), fmaxf(s[i][2], s[i][3]));
#pragma unroll
            for (int off = 1; off < 16; off <<= 1)
                rm = fmaxf(rm, __shfl_xor_sync(0xffffffffu, rm, off));
            float nm = fmaxf(m[i], rm);
            if (nm == -INFINITY) {
                corr[i] = 1.0f;
#pragma unroll
                for (int j = 0; j < 4; ++j) p[i][j] = 0.0f;
            } else {
                corr[i] = __expf(m[i] - nm);
#pragma unroll
                for (int j = 0; j < 4; ++j) p[i][j] = __expf(s[i][j] - nm);
                m[i] = nm;
            }
            float ps = (p[i][0] + p[i][1]) + (p[i][2] + p[i][3]);
#pragma unroll
            for (int off = 1; off < 16; off <<= 1)
                ps += __shfl_xor_sync(0xffffffffu, ps, off);
            psum[i] = ps;
        }

        __syncthreads();
#pragma unroll
        for (int i = 0; i < 4; ++i) {
            int r = ty * 4 + i;
            float* dst = (float*)(KP + r * 16 + ((tx + (r >> 2)) & 15));
#pragma unroll
            for (int j = 0; j < 4; ++j) dst[j] = p[i][j];
        }
#pragma unroll
        for (int i = 0; i < 4; ++i) {
            l[i] = l[i] * corr[i] + psum[i];
#pragma unroll
            for (int c = 0; c < 4; ++c) o[i][c] *= corr[i];
        }
        __syncthreads();

        for (int kk4 = 0; kk4 < 16; ++kk4) {
            float4 pv[4], vv[4];
#pragma unroll
            for (int i = 0; i < 4; ++i) pv[i] = *tsl(KP, ty * 4 + i, kk4);
#pragma unroll
            for (int u = 0; u < 4; ++u) vv[u] = *tsl(Vs, kk4 * 4 + u, tx);
#pragma unroll
            for (int i = 0; i < 4; ++i) {
                o[i][0] = fmaf(pv[i].x, vv[0].x, o[i][0]);
                o[i][1] = fmaf(pv[i].x, vv[0].y, o[i][1]);
                o[i][2] = fmaf(pv[i].x, vv[0].z, o[i][2]);
                o[i][3] = fmaf(pv[i].x, vv[0].w, o[i][3]);
                o[i][0] = fmaf(pv[i].y, vv[1].x, o[i][0]);
                o[i][1] = fmaf(pv[i].y, vv[1].y, o[i][1]);
                o[i][2] = fmaf(pv[i].y, vv[1].z, o[i][2]);
                o[i][3] = fmaf(pv[i].y, vv[1].w, o[i][3]);
                o[i][0] = fmaf(pv[i].z, vv[2].x, o[i][0]);
                o[i][1] = fmaf(pv[i].z, vv[2].y, o[i][1]);
                o[i][2] = fmaf(pv[i].z, vv[2].z, o[i][2]);
                o[i][3] = fmaf(pv[i].z, vv[2].w, o[i][3]);
                o[i][0] = fmaf(pv[i].w, vv[3].x, o[i][0]);
                o[i][1] = fmaf(pv[i].w, vv[3].y, o[i][1]);
                o[i][2] = fmaf(pv[i].w, vv[3].z, o[i][2]);
                o[i][3] = fmaf(pv[i].w, vv[3].w, o[i][3]);
            }
        }
    }

#pragma unroll
    for (int i = 0; i < 4; ++i) {
        float inv = (l[i] > 0.0f) ? (1.0f / l[i]) : 0.0f;
        float4 r = make_float4(o[i][0] * inv, o[i][1] * inv, o[i][2] * inv, o[i][3] * inv);
        size_t off = (size_t)(b * S_ + q0 + ty * 4 + i) * D_ + h * DH_ + tx * 4;
        split_store4(ch, cl, off, r);
    }
}

#define ATT_SMEM (3 * 64 * 16 * 16)   // 49152 bytes

// ---------------- launcher ----------------
extern "C" void kernel_launch(void* const* d_in, const int* in_sizes, int n_in,
                              void* d_out, int out_size) {
    const float* video    = (const float*)d_in[0];
    const float* question = (const float*)d_in[1];
    const int*   mask     = (const int*)d_in[2];
    const float* pos_emb  = (const float*)d_in[3];
    const float* mod_emb  = (const float*)d_in[4];
    const float* Wv   = (const float*)d_in[5];
    const float* bv   = (const float*)d_in[6];
    const float* nv_g = (const float*)d_in[7];
    const float* nv_b = (const float*)d_in[8];
    const float* emb_g = (const float*)d_in[9];
    const float* emb_b = (const float*)d_in[10];
    const float* Wq  = (const float*)d_in[11];
    const float* bq  = (const float*)d_in[12];
    const float* Wk  = (const float*)d_in[13];
    const float* bk  = (const float*)d_in[14];
    const float* Wva = (const float*)d_in[15];
    const float* bva = (const float*)d_in[16];
    const float* Wo  = (const float*)d_in[17];
    const float* bo  = (const float*)d_in[18];
    const float* ln1_g = (const float*)d_in[19];
    const float* ln1_b = (const float*)d_in[20];
    const float* W1  = (const float*)d_in[21];
    const float* b1  = (const float*)d_in[22];
    const float* W2  = (const float*)d_in[23];
    const float* b2  = (const float*)d_in[24];
    const float* ln2_g = (const float*)d_in[25];
    const float* ln2_b = (const float*)d_in[26];
    float* out = (float*)d_out;

    float *x, *qkv, *yb, *vproj, *bqkv;
    __half *wh, *xh, *xl, *ch, *cl, *hh, *hl, *vh, *vl;
    cudaGetSymbolAddress((void**)&x,     g_x);
    cudaGetSymbolAddress((void**)&qkv,   g_qkv);
    cudaGetSymbolAddress((void**)&yb,    g_y);
    cudaGetSymbolAddress((void**)&vproj, g_vproj);
    cudaGetSymbolAddress((void**)&bqkv,  g_bqkv);
    cudaGetSymbolAddress((void**)&wh,    g_wh);
    cudaGetSymbolAddress((void**)&xh,    g_xh);
    cudaGetSymbolAddress((void**)&xl,    g_xl);
    cudaGetSymbolAddress((void**)&ch,    g_ch);
    cudaGetSymbolAddress((void**)&cl,    g_cl);
    cudaGetSymbolAddress((void**)&hh,    g_hh);
    cudaGetSymbolAddress((void**)&hl,    g_hl);
    cudaGetSymbolAddress((void**)&vh,    g_vh);
    cudaGetSymbolAddress((void**)&vl,    g_vl);

    static bool attr_set = false;
    if (!attr_set) {
        cudaFuncSetAttribute(attn_tile_kernel, cudaFuncAttributeMaxDynamicSharedMemorySize, ATT_SMEM);
        cudaFuncSetAttribute(gemm_fp16<0>, cudaFuncAttributeMaxDynamicSharedMemorySize, GT2_SMEM);
        cudaFuncSetAttribute(gemm_fp16<2>, cudaFuncAttributeMaxDynamicSharedMemorySize, GT2_SMEM);
        attr_set = true;
    }

    const size_t o_wv = 0;
    const size_t LSTRIDE = 4 * (size_t)D_ * D_ + 2 * (size_t)D_ * FF_;
    const size_t o_l0 = o_wv + (size_t)D_ * FD_;
    auto o_wq = [&](int i) { return o_l0 + i * LSTRIDE + 0 * (size_t)D_ * D_; };
    auto o_wk = [&](int i) { return o_l0 + i * LSTRIDE + 1 * (size_t)D_ * D_; };
    auto o_wa = [&](int i) { return o_l0 + i * LSTRIDE + 2 * (size_t)D_ * D_; };
    auto o_wo = [&](int i) { return o_l0 + i * LSTRIDE + 3 * (size_t)D_ * D_; };
    auto o_w1 = [&](int i) { return o_l0 + i * LSTRIDE + 4 * (size_t)D_ * D_; };
    auto o_w2 = [&](int i) { return o_l0 + i * LSTRIDE + 4 * (size_t)D_ * D_ + (size_t)FF_ * D_; };

    split_w_kernel<<<dim3(D_ / 32, FD_ / 32), dim3(32, 8)>>>(Wv, FD_, D_, wh + o_wv);
    for (int i = 0; i < 2; ++i) {
        split_w_kernel<<<dim3(D_ / 32, D_ / 32), dim3(32, 8)>>>(Wq + (size_t)i * D_ * D_, D_, D_, wh + o_wq(i));
        split_w_kernel<<<dim3(D_ / 32, D_ / 32), dim3(32, 8)>>>(Wk + (size_t)i * D_ * D_, D_, D_, wh + o_wk(i));
        split_w_kernel<<<dim3(D_ / 32, D_ / 32), dim3(32, 8)>>>(Wva + (size_t)i * D_ * D_, D_, D_, wh + o_wa(i));
        split_w_kernel<<<dim3(D_ / 32, D_ / 32), dim3(32, 8)>>>(Wo + (size_t)i * D_ * D_, D_, D_, wh + o_wo(i));
        split_w_kernel<<<dim3(FF_ / 32, D_ / 32), dim3(32, 8)>>>(W1 + (size_t)i * D_ * FF_, D_, FF_, wh + o_w1(i));
        split_w_kernel<<<dim3(D_ / 32, FF_ / 32), dim3(32, 8)>>>(W2 + (size_t)i * FF_ * D_, FF_, D_, wh + o_w2(i));
        concat_bias_kernel<<<6, 256>>>(bq + i * D_, bk + i * D_, bva + i * D_, bqkv + i * LDQKV);
    }

    // video split + projection
    split_a_kernel<<<(BT_ * FD_) / 1024, 256>>>(video, vh, vl);
    gemm_fp16<0><<<dim3(D_ / 128, BT_ / 128), 256, GT2_SMEM>>>(vh, vl, wh + o_wv, bv,
                                                               vproj, nullptr, nullptr, BT_, D_, FD_, 1.0f, 0);
    build_x_kernel<<<BS_, 128>>>(question, vproj, pos_emb, mod_emb, nv_g, nv_b, emb_g, emb_b, x, xh, xl);

    const float scale = 0.125f;
    for (int i = 0; i < 2; ++i) {
        // fused QKV: W rows [0,512)=Wq, [512,1024)=Wk, [1024,1536)=Wva (contiguous in split layout)
        gemm_fp16<0><<<dim3(LDQKV / 128, BS_ / 128), 256, GT2_SMEM>>>(xh, xl, wh + o_wq(i),
                                                                      bqkv + i * LDQKV, qkv, nullptr, nullptr,
                                                                      BS_, LDQKV, D_, scale, 512);

        attn_tile_kernel<<<dim3(B_ * H_, S_ / 64), 256, ATT_SMEM>>>(qkv, mask, ch, cl);

        gemm_fp16<0><<<dim3(D_ / 128, BS_ / 128), 256, GT2_SMEM>>>(ch, cl, wh + o_wo(i), bo + i * D_,
                                                                   yb, nullptr, nullptr, BS_, D_, D_, 1.0f, 0);
        add_ln_kernel<<<BS_, 128>>>(yb, x, x, xh, xl, ln1_g + i * D_, ln1_b + i * D_);

        gemm_fp16<2><<<dim3(FF_ / 128, BS_ / 128), 256, GT2_SMEM>>>(xh, xl, wh + o_w1(i), b1 + i * FF_,
                                                                    nullptr, hh, hl, BS_, FF_, D_, 1.0f, 0);
        gemm_fp16<0><<<dim3(D_ / 128, BS_ / 128), 256, GT2_SMEM>>>(hh, hl, wh + o_w2(i), b2 + i * D_,
                                                                   yb, nullptr, nullptr, BS_, D_, FF_, 1.0f, 0);

        float* dst = (i == 1) ? out : x;
        add_ln_kernel<<<BS_, 128>>>(yb, x, dst, xh, xl, ln2_g + i * D_, ln2_b + i * D_);
    }
    (void)in_sizes; (void)n_in; (void)out_size;
}

// round 12
// speedup vs baseline: 1.6129x; 1.2455x over previous
#include <cuda_runtime.h>
#include <cuda_fp16.h>
#include <math.h>
#include <stdint.h>

#define B_   64
#define Q_   64
#define T_   448
#define D_   512
#define FD_  1024
#define H_   8
#define DH_  64
#define FF_  2048
#define S_   512
#define BS_  (B_ * S_)   // 32768
#define BT_  (B_ * T_)   // 28672
#define LDQKV 1536

// ---------------- scratch (static device globals; no allocation) ----------------
__device__ float g_x[BS_ * D_];
__device__ float g_qkv[(size_t)BS_ * LDQKV];
__device__ float g_y[BS_ * D_];
__device__ float g_vproj[(size_t)BT_ * D_];
__device__ float g_bqkv[2 * LDQKV];

// fp16 activations (single precision-split dropped)
__device__ __half g_xh[BS_ * D_];
__device__ __half g_ch[BS_ * D_];
__device__ __half g_hh[(size_t)BS_ * FF_];
__device__ __half g_vh[(size_t)BT_ * FD_];

// transposed weights: fp16, layout [N][K]
#define WSPLIT_TOTAL 6815744
__device__ __half g_wh[WSPLIT_TOTAL];

// ---------------- small helpers ----------------
__device__ __forceinline__ float4 ld4(const float* p) { return *(const float4*)p; }
__device__ __forceinline__ void st4(float* p, float4 v) { *(float4*)p = v; }

__device__ __forceinline__ void h4_store(__half* __restrict__ hp, size_t off, float4 v) {
    __half h0 = __float2half_rn(v.x);
    __half h1 = __float2half_rn(v.y);
    __half h2 = __float2half_rn(v.z);
    __half h3 = __float2half_rn(v.w);
    *(__half2*)(hp + off)     = __halves2half2(h0, h1);
    *(__half2*)(hp + off + 2) = __halves2half2(h2, h3);
}

__device__ __forceinline__ float block_sum(float v, float* sm) {
#pragma unroll
    for (int o = 16; o; o >>= 1) v += __shfl_xor_sync(0xffffffffu, v, o);
    int w = threadIdx.x >> 5;
    __syncthreads();
    if ((threadIdx.x & 31) == 0) sm[w] = v;
    __syncthreads();
    return (sm[0] + sm[1]) + (sm[2] + sm[3]);
}

__device__ __forceinline__ void block_ln(float4& v, int i0,
                                         const float* __restrict__ g,
                                         const float* __restrict__ b,
                                         float* sm) {
    float s = v.x + v.y + v.z + v.w;
    s = block_sum(s, sm);
    float mean = s * (1.0f / (float)D_);
    float dx = v.x - mean, dy = v.y - mean, dz = v.z - mean, dw = v.w - mean;
    float ss = dx * dx + dy * dy + dz * dz + dw * dw;
    ss = block_sum(ss, sm);
    float inv = rsqrtf(ss * (1.0f / (float)D_) + 1e-12f);
    float4 gg = ld4(g + i0), bb = ld4(b + i0);
    v.x = dx * inv * gg.x + bb.x;
    v.y = dy * inv * gg.y + bb.y;
    v.z = dz * inv * gg.z + bb.z;
    v.w = dw * inv * gg.w + bb.w;
}

// ---------------- weight transpose: T[n][k] = fp16(W[k][n]) ----------------
__global__ void split_w_kernel(const float* __restrict__ W, int K, int N,
                               __half* __restrict__ Th) {
    __shared__ float tile[32][33];
    int k0 = blockIdx.y * 32, n0 = blockIdx.x * 32;
    int tx = threadIdx.x, ty = threadIdx.y;
    for (int j = ty; j < 32; j += 8)
        tile[j][tx] = W[(size_t)(k0 + j) * N + n0 + tx];
    __syncthreads();
    for (int j = ty; j < 32; j += 8) {
        size_t o = (size_t)(n0 + j) * K + k0 + tx;
        Th[o] = __float2half_rn(tile[tx][j]);
    }
}

// ---------------- plain elementwise convert (video) ----------------
__global__ void split_a_kernel(const float* __restrict__ A, __half* __restrict__ Ah) {
    size_t i = ((size_t)blockIdx.x * 256 + threadIdx.x) * 4;
    float4 v = ld4(A + i);
    h4_store(Ah, i, v);
}

// ---------------- concat qkv bias ----------------
__global__ void concat_bias_kernel(const float* __restrict__ bq, const float* __restrict__ bk,
                                   const float* __restrict__ bv, float* __restrict__ dst) {
    int i = blockIdx.x * 256 + threadIdx.x;
    if (i < LDQKV)
        dst[i] = (i < 512) ? bq[i] : ((i < 1024) ? bk[i - 512] : bv[i - 1024]);
}

// ---------------- mma.sync GEMM: fp16 single-pass, 2-stage cp.async, occ 2 ----------------
// C = epilogue(A @ W^T + bias); A [M][K] fp16, W [N][K] fp16
// MODE 0: f32 out, cols < scale_cols multiplied by scale
// MODE 2: gelu -> fp16 out
#define GLDA 40
#define ARR  (128 * GLDA)
#define BUFE (2 * ARR)
#define GT2_SMEM (2 * BUFE * 2)   // 40960 bytes, 2 CTAs/SM

__device__ __forceinline__ void mma16816(float* d, const unsigned* a, const unsigned* b) {
    asm volatile(
        "mma.sync.aligned.m16n8k16.row.col.f32.f16.f16.f32 "
        "{%0,%1,%2,%3}, {%4,%5,%6,%7}, {%8,%9}, {%0,%1,%2,%3};\n"
        : "+f"(d[0]), "+f"(d[1]), "+f"(d[2]), "+f"(d[3])
        : "r"(a[0]), "r"(a[1]), "r"(a[2]), "r"(a[3]), "r"(b[0]), "r"(b[1]));
}
__device__ __forceinline__ void ldsm4(unsigned* r, unsigned addr) {
    asm volatile("ldmatrix.sync.aligned.m8n8.x4.shared.b16 {%0,%1,%2,%3}, [%4];\n"
                 : "=r"(r[0]), "=r"(r[1]), "=r"(r[2]), "=r"(r[3]) : "r"(addr));
}
__device__ __forceinline__ void ldsm2(unsigned* r, unsigned addr) {
    asm volatile("ldmatrix.sync.aligned.m8n8.x2.shared.b16 {%0,%1}, [%2];\n"
                 : "=r"(r[0]), "=r"(r[1]) : "r"(addr));
}
__device__ __forceinline__ void cpasync16(uint32_t dst, const void* src) {
    asm volatile("cp.async.cg.shared.global [%0], [%1], 16;" :: "r"(dst), "l"(src));
}
#define CP_COMMIT() asm volatile("cp.async.commit_group;" ::: "memory")
#define CP_WAIT1()  asm volatile("cp.async.wait_group 1;" ::: "memory")
#define CP_WAIT0()  asm volatile("cp.async.wait_group 0;" ::: "memory")

template<int MODE>
__global__ __launch_bounds__(256, 2)
void gemm_fp16(const __half* __restrict__ Ah_g,
               const __half* __restrict__ Wh_g,
               const float* __restrict__ bias,
               float* __restrict__ C,
               __half* __restrict__ Ch,
               int M, int N, int K, float scale, int scale_cols) {
    extern __shared__ __half smg[];

    int tid = threadIdx.x;
    int lane = tid & 31, wid = tid >> 5;
    int warpM = wid & 1, warpN = wid >> 1;
    int m0 = warpM * 64, n0 = warpN * 32;

    int blockM = blockIdx.y * 128;
    int blockN = blockIdx.x * 128;

    int a_row = lane & 15, a_cs = (lane >> 4) * 8;
    int b_row = lane & 7,  b_cs = ((lane >> 3) & 1) * 8;

    float acc[4][4][4];
#pragma unroll
    for (int f = 0; f < 4; ++f)
#pragma unroll
        for (int g = 0; g < 4; ++g)
#pragma unroll
            for (int j = 0; j < 4; ++j) acc[f][g][j] = 0.0f;

    int sr[2], sc[2];
#pragma unroll
    for (int wv = 0; wv < 2; ++wv) {
        int idx = tid + wv * 256;
        sr[wv] = idx >> 2;
        sc[wv] = (idx & 3) * 8;
    }

    auto stage = [&](int kt, int buf) {
        __half* base = smg + buf * BUFE;
#pragma unroll
        for (int wv = 0; wv < 2; ++wv) {
            int r = sr[wv], c8 = sc[wv];
            uint32_t dsm = (uint32_t)__cvta_generic_to_shared(base + r * GLDA + c8);
            size_t ga = (size_t)(blockM + r) * K + kt * 32 + c8;
            size_t gb = (size_t)(blockN + r) * K + kt * 32 + c8;
            cpasync16(dsm,           Ah_g + ga);
            cpasync16(dsm + ARR * 2, Wh_g + gb);
        }
        CP_COMMIT();
    };

    int T = K >> 5;
    stage(0, 0);

    for (int kt = 0; kt < T; ++kt) {
        int buf = kt & 1;
        if (kt + 1 < T) { stage(kt + 1, buf ^ 1); CP_WAIT1(); }
        else            { CP_WAIT0(); }
        __syncthreads();

        __half* Ahs = smg + buf * BUFE;
        __half* Bhs = Ahs + ARR;

#pragma unroll
        for (int kc = 0; kc < 32; kc += 16) {
            unsigned aF[16], bHf[8];
#pragma unroll
            for (int f = 0; f < 4; ++f)
                ldsm4(aF + 4 * f, (unsigned)__cvta_generic_to_shared(
                    Ahs + (m0 + f * 16 + a_row) * GLDA + kc + a_cs));
#pragma unroll
            for (int g = 0; g < 4; ++g)
                ldsm2(bHf + 2 * g, (unsigned)__cvta_generic_to_shared(
                    Bhs + (n0 + g * 8 + b_row) * GLDA + kc + b_cs));
#pragma unroll
            for (int f = 0; f < 4; ++f)
#pragma unroll
                for (int g = 0; g < 4; ++g)
                    mma16816(acc[f][g], aF + 4 * f, bHf + 2 * g);
        }
        __syncthreads();
    }

    // ---- epilogue ----
    bool do_scale = (MODE == 0) && (blockN < scale_cols);
#pragma unroll
    for (int f = 0; f < 4; ++f) {
#pragma unroll
        for (int g = 0; g < 4; ++g) {
            int col = blockN + n0 + g * 8 + (lane & 3) * 2;
            float b0 = bias[col], b1 = bias[col + 1];
#pragma unroll
            for (int half_ = 0; half_ < 2; ++half_) {
                int row = blockM + m0 + f * 16 + (lane >> 2) + half_ * 8;
                float v0 = acc[f][g][half_ * 2 + 0] + b0;
                float v1 = acc[f][g][half_ * 2 + 1] + b1;
                if (MODE == 0) {
                    if (do_scale) { v0 *= scale; v1 *= scale; }
                    *(float2*)&C[(size_t)row * N + col] = make_float2(v0, v1);
                } else {
                    v0 = 0.5f * v0 * (1.0f + erff(v0 * 0.70710678118654752f));
                    v1 = 0.5f * v1 * (1.0f + erff(v1 * 0.70710678118654752f));
                    size_t off = (size_t)row * N + col;
                    *(__half2*)(Ch + off) = __halves2half2(__float2half_rn(v0), __float2half_rn(v1));
                }
            }
        }
    }
}

// ---------------- build x ----------------
__global__ void build_x_kernel(const float* __restrict__ question,
                               const float* __restrict__ vproj,
                               const float* __restrict__ pos_emb,
                               const float* __restrict__ mod_emb,
                               const float* __restrict__ nv_g, const float* __restrict__ nv_b,
                               const float* __restrict__ emb_g, const float* __restrict__ emb_b,
                               float* __restrict__ x,
                               __half* __restrict__ xh) {
    __shared__ float sm[4];
    int row = blockIdx.x;
    int b = row / S_, s = row % S_;
    int i0 = threadIdx.x * 4;
    float4 v;
    if (s < Q_) {
        v = ld4(question + ((size_t)b * Q_ + s) * D_ + i0);
    } else {
        v = ld4(vproj + ((size_t)b * T_ + (s - Q_)) * D_ + i0);
        block_ln(v, i0, nv_g, nv_b, sm);
    }
    float4 pe = ld4(pos_emb + (size_t)s * D_ + i0);
    const float* me_p = mod_emb + (size_t)(s < Q_ ? 0 : 1) * D_ + i0;
    float4 me = ld4(me_p);
    v.x += pe.x + me.x; v.y += pe.y + me.y; v.z += pe.z + me.z; v.w += pe.w + me.w;
    block_ln(v, i0, emb_g, emb_b, sm);
    size_t off = (size_t)row * D_ + i0;
    st4(x + off, v);
    h4_store(xh, off, v);
}

// ---------------- residual + LN ----------------
__global__ void add_ln_kernel(const float* __restrict__ y, const float* __restrict__ res,
                              float* __restrict__ out,
                              __half* __restrict__ oh,
                              const float* __restrict__ g, const float* __restrict__ bta) {
    __shared__ float sm[4];
    int row = blockIdx.x;
    int i0 = threadIdx.x * 4;
    size_t off = (size_t)row * D_ + i0;
    float4 a = ld4(y + off), r = ld4(res + off);
    float4 v = make_float4(a.x + r.x, a.y + r.y, a.z + r.z, a.w + r.w);
    block_ln(v, i0, g, bta, sm);
    st4(out + off, v);
    h4_store(oh, off, v);
}

// ---------------- tiled flash attention (reads fused qkv, stride LDQKV) ----------------
__device__ __forceinline__ float4* tsl(float4* base, int r, int c4) {
    return base + r * 16 + ((c4 + (r >> 2)) & 15);
}

__global__ __launch_bounds__(256)
void attn_tile_kernel(const float* __restrict__ qkv, const int* __restrict__ mask,
                      __half* __restrict__ ch) {
    extern __shared__ float smdyn[];
    float4* Qs = (float4*)smdyn;
    float4* KP = Qs + 1024;
    float4* Vs = KP + 1024;
    __shared__ int ms[64];

    int bh = blockIdx.x;
    int b = bh >> 3, h = bh & 7;
    int q0 = blockIdx.y * 64;
    int tid = threadIdx.x;
    int tx = tid & 15, ty = tid >> 4;

    const float* qb = qkv + (size_t)b * S_ * LDQKV + h * DH_;
    const float* kb = qb + 512;
    const float* vb = qb + 1024;

    {
        int r = tid >> 2, c4 = (tid & 3) * 4;
        const float* src = qb + (size_t)(q0 + r) * LDQKV + c4 * 4;
#pragma unroll
        for (int u = 0; u < 4; ++u)
            *tsl(Qs, r, c4 + u) = ld4(src + u * 4);
    }

    float m[4], l[4], o[4][4];
#pragma unroll
    for (int i = 0; i < 4; ++i) {
        m[i] = -INFINITY; l[i] = 0.0f;
#pragma unroll
        for (int c = 0; c < 4; ++c) o[i][c] = 0.0f;
    }

    for (int kt = 0; kt < 8; ++kt) {
        int k0 = kt * 64;
        __syncthreads();
        {
            int r = tid >> 2, c4 = (tid & 3) * 4;
            const float* ks = kb + (size_t)(k0 + r) * LDQKV + c4 * 4;
            const float* vs = vb + (size_t)(k0 + r) * LDQKV + c4 * 4;
#pragma unroll
            for (int u = 0; u < 4; ++u) {
                *tsl(KP, r, c4 + u) = ld4(ks + u * 4);
                *tsl(Vs, r, c4 + u) = ld4(vs + u * 4);
            }
            if (tid < 64) ms[tid] = mask[b * S_ + k0 + tid];
        }
        __syncthreads();

        float s[4][4];
#pragma unroll
        for (int i = 0; i < 4; ++i)
#pragma unroll
            for (int j = 0; j < 4; ++j) s[i][j] = 0.0f;

        for (int d4 = 0; d4 < 16; ++d4) {
            float4 qv[4], kv[4];
#pragma unroll
            for (int i = 0; i < 4; ++i) qv[i] = *tsl(Qs, ty * 4 + i, d4);
#pragma unroll
            for (int j = 0; j < 4; ++j) kv[j] = *tsl(KP, tx * 4 + j, d4);
#pragma unroll
            for (int i = 0; i < 4; ++i)
#pragma unroll
                for (int j = 0; j < 4; ++j) {
                    s[i][j] = fmaf(qv[i].x, kv[j].x, s[i][j]);
                    s[i][j] = fmaf(qv[i].y, kv[j].y, s[i][j]);
                    s[i][j] = fmaf(qv[i].z, kv[j].z, s[i][j]);
                    s[i][j] = fmaf(qv[i].w, kv[j].w, s[i][j]);
                }
        }
#pragma unroll
        for (int j = 0; j < 4; ++j) {
            if (ms[tx * 4 + j] == 0) {
#pragma unroll
                for (int i = 0; i < 4; ++i) s[i][j] = -INFINITY;
            }
        }

        float p[4][4], corr[4], psum[4];
#pragma unroll
        for (int i = 0; i < 4; ++i) {
            float rm = fmaxf(fmaxf(s[i][0], s[i][1]), fmaxf(s[i][2], s[i][3]));
#pragma unroll
            for (int off = 1; off < 16; off <<= 1)
                rm = fmaxf(rm, __shfl_xor_sync(0xffffffffu, rm, off));
            float nm = fmaxf(m[i], rm);
            if (nm == -INFINITY) {
                corr[i] = 1.0f;
#pragma unroll
                for (int j = 0; j < 4; ++j) p[i][j] = 0.0f;
            } else {
                corr[i] = __expf(m[i] - nm);
#pragma unroll
                for (int j = 0; j < 4; ++j) p[i][j] = __expf(s[i][j] - nm);
                m[i] = nm;
            }
            float ps = (p[i][0] + p[i][1]) + (p[i][2] + p[i][3]);
#pragma unroll
            for (int off = 1; off < 16; off <<= 1)
                ps += __shfl_xor_sync(0xffffffffu, ps, off);
            psum[i] = ps;
        }

        __syncthreads();
#pragma unroll
        for (int i = 0; i < 4; ++i) {
            int r = ty * 4 + i;
            float* dst = (float*)(KP + r * 16 + ((tx + (r >> 2)) & 15));
#pragma unroll
            for (int j = 0; j < 4; ++j) dst[j] = p[i][j];
        }
#pragma unroll
        for (int i = 0; i < 4; ++i) {
            l[i] = l[i] * corr[i] + psum[i];
#pragma unroll
            for (int c = 0; c < 4; ++c) o[i][c] *= corr[i];
        }
        __syncthreads();

        for (int kk4 = 0; kk4 < 16; ++kk4) {
            float4 pv[4], vv[4];
#pragma unroll
            for (int i = 0; i < 4; ++i) pv[i] = *tsl(KP, ty * 4 + i, kk4);
#pragma unroll
            for (int u = 0; u < 4; ++u) vv[u] = *tsl(Vs, kk4 * 4 + u, tx);
#pragma unroll
            for (int i = 0; i < 4; ++i) {
                o[i][0] = fmaf(pv[i].x, vv[0].x, o[i][0]);
                o[i][1] = fmaf(pv[i].x, vv[0].y, o[i][1]);
                o[i][2] = fmaf(pv[i].x, vv[0].z, o[i][2]);
                o[i][3] = fmaf(pv[i].x, vv[0].w, o[i][3]);
                o[i][0] = fmaf(pv[i].y, vv[1].x, o[i][0]);
                o[i][1] = fmaf(pv[i].y, vv[1].y, o[i][1]);
                o[i][2] = fmaf(pv[i].y, vv[1].z, o[i][2]);
                o[i][3] = fmaf(pv[i].y, vv[1].w, o[i][3]);
                o[i][0] = fmaf(pv[i].z, vv[2].x, o[i][0]);
                o[i][1] = fmaf(pv[i].z, vv[2].y, o[i][1]);
                o[i][2] = fmaf(pv[i].z, vv[2].z, o[i][2]);
                o[i][3] = fmaf(pv[i].z, vv[2].w, o[i][3]);
                o[i][0] = fmaf(pv[i].w, vv[3].x, o[i][0]);
                o[i][1] = fmaf(pv[i].w, vv[3].y, o[i][1]);
                o[i][2] = fmaf(pv[i].w, vv[3].z, o[i][2]);
                o[i][3] = fmaf(pv[i].w, vv[3].w, o[i][3]);
            }
        }
    }

#pragma unroll
    for (int i = 0; i < 4; ++i) {
        float inv = (l[i] > 0.0f) ? (1.0f / l[i]) : 0.0f;
        float4 r = make_float4(o[i][0] * inv, o[i][1] * inv, o[i][2] * inv, o[i][3] * inv);
        size_t off = (size_t)(b * S_ + q0 + ty * 4 + i) * D_ + h * DH_ + tx * 4;
        h4_store(ch, off, r);
    }
}

#define ATT_SMEM (3 * 64 * 16 * 16)   // 49152 bytes

// ---------------- launcher ----------------
extern "C" void kernel_launch(void* const* d_in, const int* in_sizes, int n_in,
                              void* d_out, int out_size) {
    const float* video    = (const float*)d_in[0];
    const float* question = (const float*)d_in[1];
    const int*   mask     = (const int*)d_in[2];
    const float* pos_emb  = (const float*)d_in[3];
    const float* mod_emb  = (const float*)d_in[4];
    const float* Wv   = (const float*)d_in[5];
    const float* bv   = (const float*)d_in[6];
    const float* nv_g = (const float*)d_in[7];
    const float* nv_b = (const float*)d_in[8];
    const float* emb_g = (const float*)d_in[9];
    const float* emb_b = (const float*)d_in[10];
    const float* Wq  = (const float*)d_in[11];
    const float* bq  = (const float*)d_in[12];
    const float* Wk  = (const float*)d_in[13];
    const float* bk  = (const float*)d_in[14];
    const float* Wva = (const float*)d_in[15];
    const float* bva = (const float*)d_in[16];
    const float* Wo  = (const float*)d_in[17];
    const float* bo  = (const float*)d_in[18];
    const float* ln1_g = (const float*)d_in[19];
    const float* ln1_b = (const float*)d_in[20];
    const float* W1  = (const float*)d_in[21];
    const float* b1  = (const float*)d_in[22];
    const float* W2  = (const float*)d_in[23];
    const float* b2  = (const float*)d_in[24];
    const float* ln2_g = (const float*)d_in[25];
    const float* ln2_b = (const float*)d_in[26];
    float* out = (float*)d_out;

    float *x, *qkv, *yb, *vproj, *bqkv;
    __half *wh, *xh, *ch, *hh, *vh;
    cudaGetSymbolAddress((void**)&x,     g_x);
    cudaGetSymbolAddress((void**)&qkv,   g_qkv);
    cudaGetSymbolAddress((void**)&yb,    g_y);
    cudaGetSymbolAddress((void**)&vproj, g_vproj);
    cudaGetSymbolAddress((void**)&bqkv,  g_bqkv);
    cudaGetSymbolAddress((void**)&wh,    g_wh);
    cudaGetSymbolAddress((void**)&xh,    g_xh);
    cudaGetSymbolAddress((void**)&ch,    g_ch);
    cudaGetSymbolAddress((void**)&hh,    g_hh);
    cudaGetSymbolAddress((void**)&vh,    g_vh);

    static bool attr_set = false;
    if (!attr_set) {
        cudaFuncSetAttribute(attn_tile_kernel, cudaFuncAttributeMaxDynamicSharedMemorySize, ATT_SMEM);
        cudaFuncSetAttribute(gemm_fp16<0>, cudaFuncAttributeMaxDynamicSharedMemorySize, GT2_SMEM);
        cudaFuncSetAttribute(gemm_fp16<2>, cudaFuncAttributeMaxDynamicSharedMemorySize, GT2_SMEM);
        attr_set = true;
    }

    const size_t o_wv = 0;
    const size_t LSTRIDE = 4 * (size_t)D_ * D_ + 2 * (size_t)D_ * FF_;
    const size_t o_l0 = o_wv + (size_t)D_ * FD_;
    auto o_wq = [&](int i) { return o_l0 + i * LSTRIDE + 0 * (size_t)D_ * D_; };
    auto o_wk = [&](int i) { return o_l0 + i * LSTRIDE + 1 * (size_t)D_ * D_; };
    auto o_wa = [&](int i) { return o_l0 + i * LSTRIDE + 2 * (size_t)D_ * D_; };
    auto o_wo = [&](int i) { return o_l0 + i * LSTRIDE + 3 * (size_t)D_ * D_; };
    auto o_w1 = [&](int i) { return o_l0 + i * LSTRIDE + 4 * (size_t)D_ * D_; };
    auto o_w2 = [&](int i) { return o_l0 + i * LSTRIDE + 4 * (size_t)D_ * D_ + (size_t)FF_ * D_; };

    split_w_kernel<<<dim3(D_ / 32, FD_ / 32), dim3(32, 8)>>>(Wv, FD_, D_, wh + o_wv);
    for (int i = 0; i < 2; ++i) {
        split_w_kernel<<<dim3(D_ / 32, D_ / 32), dim3(32, 8)>>>(Wq + (size_t)i * D_ * D_, D_, D_, wh + o_wq(i));
        split_w_kernel<<<dim3(D_ / 32, D_ / 32), dim3(32, 8)>>>(Wk + (size_t)i * D_ * D_, D_, D_, wh + o_wk(i));
        split_w_kernel<<<dim3(D_ / 32, D_ / 32), dim3(32, 8)>>>(Wva + (size_t)i * D_ * D_, D_, D_, wh + o_wa(i));
        split_w_kernel<<<dim3(D_ / 32, D_ / 32), dim3(32, 8)>>>(Wo + (size_t)i * D_ * D_, D_, D_, wh + o_wo(i));
        split_w_kernel<<<dim3(FF_ / 32, D_ / 32), dim3(32, 8)>>>(W1 + (size_t)i * D_ * FF_, D_, FF_, wh + o_w1(i));
        split_w_kernel<<<dim3(D_ / 32, FF_ / 32), dim3(32, 8)>>>(W2 + (size_t)i * FF_ * D_, FF_, D_, wh + o_w2(i));
        concat_bias_kernel<<<6, 256>>>(bq + i * D_, bk + i * D_, bva + i * D_, bqkv + i * LDQKV);
    }

    // video convert + projection
    split_a_kernel<<<(BT_ * FD_) / 1024, 256>>>(video, vh);
    gemm_fp16<0><<<dim3(D_ / 128, BT_ / 128), 256, GT2_SMEM>>>(vh, wh + o_wv, bv,
                                                               vproj, nullptr, BT_, D_, FD_, 1.0f, 0);
    build_x_kernel<<<BS_, 128>>>(question, vproj, pos_emb, mod_emb, nv_g, nv_b, emb_g, emb_b, x, xh);

    const float scale = 0.125f;
    for (int i = 0; i < 2; ++i) {
        // fused QKV: W rows [0,512)=Wq, [512,1024)=Wk, [1024,1536)=Wva (contiguous in split layout)
        gemm_fp16<0><<<dim3(LDQKV / 128, BS_ / 128), 256, GT2_SMEM>>>(xh, wh + o_wq(i),
                                                                      bqkv + i * LDQKV, qkv, nullptr,
                                                                      BS_, LDQKV, D_, scale, 512);

        attn_tile_kernel<<<dim3(B_ * H_, S_ / 64), 256, ATT_SMEM>>>(qkv, mask, ch);

        gemm_fp16<0><<<dim3(D_ / 128, BS_ / 128), 256, GT2_SMEM>>>(ch, wh + o_wo(i), bo + i * D_,
                                                                   yb, nullptr, BS_, D_, D_, 1.0f, 0);
        add_ln_kernel<<<BS_, 128>>>(yb, x, x, xh, ln1_g + i * D_, ln1_b + i * D_);

        gemm_fp16<2><<<dim3(FF_ / 128, BS_ / 128), 256, GT2_SMEM>>>(xh, wh + o_w1(i), b1 + i * FF_,
                                                                    nullptr, hh, BS_, FF_, D_, 1.0f, 0);
        gemm_fp16<0><<<dim3(D_ / 128, BS_ / 128), 256, GT2_SMEM>>>(hh, wh + o_w2(i), b2 + i * D_,
                                                                   yb, nullptr, BS_, D_, FF_, 1.0f, 0);

        float* dst = (i == 1) ? out : x;
        add_ln_kernel<<<BS_, 128>>>(yb, x, dst, xh, ln2_g + i * D_, ln2_b + i * D_);
    }
    (void)in_sizes; (void)n_in; (void)out_size;
}

// round 13
// speedup vs baseline: 2.9932x; 1.8558x over previous
#include <cuda_runtime.h>
#include <cuda_fp16.h>
#include <math.h>
#include <stdint.h>

#define B_   64
#define Q_   64
#define T_   448
#define D_   512
#define FD_  1024
#define H_   8
#define DH_  64
#define FF_  2048
#define S_   512
#define BS_  (B_ * S_)   // 32768
#define BT_  (B_ * T_)   // 28672
#define LDQKV 1536

// ---------------- scratch (static device globals; no allocation) ----------------
__device__ float g_x[BS_ * D_];
__device__ float g_y[BS_ * D_];
__device__ float g_vproj[(size_t)BT_ * D_];
__device__ float g_bqkv[2 * LDQKV];

// fp16 activations
__device__ __half g_qkvh[(size_t)BS_ * LDQKV];
__device__ __half g_xh[BS_ * D_];
__device__ __half g_ch[BS_ * D_];
__device__ __half g_hh[(size_t)BS_ * FF_];
__device__ __half g_vh[(size_t)BT_ * FD_];

// transposed weights: fp16, layout [N][K]
#define WSPLIT_TOTAL 6815744
__device__ __half g_wh[WSPLIT_TOTAL];

// ---------------- small helpers ----------------
__device__ __forceinline__ float4 ld4(const float* p) { return *(const float4*)p; }
__device__ __forceinline__ void st4(float* p, float4 v) { *(float4*)p = v; }

__device__ __forceinline__ void h4_store(__half* __restrict__ hp, size_t off, float4 v) {
    *(__half2*)(hp + off)     = __halves2half2(__float2half_rn(v.x), __float2half_rn(v.y));
    *(__half2*)(hp + off + 2) = __halves2half2(__float2half_rn(v.z), __float2half_rn(v.w));
}

__device__ __forceinline__ float block_sum(float v, float* sm) {
#pragma unroll
    for (int o = 16; o; o >>= 1) v += __shfl_xor_sync(0xffffffffu, v, o);
    int w = threadIdx.x >> 5;
    __syncthreads();
    if ((threadIdx.x & 31) == 0) sm[w] = v;
    __syncthreads();
    return (sm[0] + sm[1]) + (sm[2] + sm[3]);
}

__device__ __forceinline__ void block_ln(float4& v, int i0,
                                         const float* __restrict__ g,
                                         const float* __restrict__ b,
                                         float* sm) {
    float s = v.x + v.y + v.z + v.w;
    s = block_sum(s, sm);
    float mean = s * (1.0f / (float)D_);
    float dx = v.x - mean, dy = v.y - mean, dz = v.z - mean, dw = v.w - mean;
    float ss = dx * dx + dy * dy + dz * dz + dw * dw;
    ss = block_sum(ss, sm);
    float inv = rsqrtf(ss * (1.0f / (float)D_) + 1e-12f);
    float4 gg = ld4(g + i0), bb = ld4(b + i0);
    v.x = dx * inv * gg.x + bb.x;
    v.y = dy * inv * gg.y + bb.y;
    v.z = dz * inv * gg.z + bb.z;
    v.w = dw * inv * gg.w + bb.w;
}

// ---------------- weight transpose: T[n][k] = fp16(W[k][n]) ----------------
__global__ void split_w_kernel(const float* __restrict__ W, int K, int N,
                               __half* __restrict__ Th) {
    __shared__ float tile[32][33];
    int k0 = blockIdx.y * 32, n0 = blockIdx.x * 32;
    int tx = threadIdx.x, ty = threadIdx.y;
    for (int j = ty; j < 32; j += 8)
        tile[j][tx] = W[(size_t)(k0 + j) * N + n0 + tx];
    __syncthreads();
    for (int j = ty; j < 32; j += 8) {
        size_t o = (size_t)(n0 + j) * K + k0 + tx;
        Th[o] = __float2half_rn(tile[tx][j]);
    }
}

// ---------------- plain elementwise convert (video) ----------------
__global__ void split_a_kernel(const float* __restrict__ A, __half* __restrict__ Ah) {
    size_t i = ((size_t)blockIdx.x * 256 + threadIdx.x) * 4;
    float4 v = ld4(A + i);
    h4_store(Ah, i, v);
}

// ---------------- concat qkv bias ----------------
__global__ void concat_bias_kernel(const float* __restrict__ bq, const float* __restrict__ bk,
                                   const float* __restrict__ bv, float* __restrict__ dst) {
    int i = blockIdx.x * 256 + threadIdx.x;
    if (i < LDQKV)
        dst[i] = (i < 512) ? bq[i] : ((i < 1024) ? bk[i - 512] : bv[i - 1024]);
}

// ---------------- mma primitives ----------------
__device__ __forceinline__ void mma16816(float* d, const unsigned* a, const unsigned* b) {
    asm volatile(
        "mma.sync.aligned.m16n8k16.row.col.f32.f16.f16.f32 "
        "{%0,%1,%2,%3}, {%4,%5,%6,%7}, {%8,%9}, {%0,%1,%2,%3};\n"
        : "+f"(d[0]), "+f"(d[1]), "+f"(d[2]), "+f"(d[3])
        : "r"(a[0]), "r"(a[1]), "r"(a[2]), "r"(a[3]), "r"(b[0]), "r"(b[1]));
}
__device__ __forceinline__ void ldsm4(unsigned* r, unsigned addr) {
    asm volatile("ldmatrix.sync.aligned.m8n8.x4.shared.b16 {%0,%1,%2,%3}, [%4];\n"
                 : "=r"(r[0]), "=r"(r[1]), "=r"(r[2]), "=r"(r[3]) : "r"(addr));
}
__device__ __forceinline__ void ldsm2(unsigned* r, unsigned addr) {
    asm volatile("ldmatrix.sync.aligned.m8n8.x2.shared.b16 {%0,%1}, [%2];\n"
                 : "=r"(r[0]), "=r"(r[1]) : "r"(addr));
}
__device__ __forceinline__ void ldsm2t(unsigned* r, unsigned addr) {
    asm volatile("ldmatrix.sync.aligned.m8n8.x2.trans.shared.b16 {%0,%1}, [%2];\n"
                 : "=r"(r[0]), "=r"(r[1]) : "r"(addr));
}
__device__ __forceinline__ void cpasync16(uint32_t dst, const void* src) {
    asm volatile("cp.async.cg.shared.global [%0], [%1], 16;" :: "r"(dst), "l"(src));
}
#define CP_COMMIT() asm volatile("cp.async.commit_group;" ::: "memory")
#define CP_WAIT1()  asm volatile("cp.async.wait_group 1;" ::: "memory")
#define CP_WAIT0()  asm volatile("cp.async.wait_group 0;" ::: "memory")

// ---------------- mma.sync GEMM: fp16 single-pass, 2-stage cp.async, occ 2 ----------------
// MODE 0: f32 out (scale on cols < scale_cols)
// MODE 1: fp16 out (scale on cols < scale_cols)
// MODE 2: gelu -> fp16 out
#define GLDA 40
#define ARR  (128 * GLDA)
#define BUFE (2 * ARR)
#define GT2_SMEM (2 * BUFE * 2)   // 40960 bytes, 2 CTAs/SM

template<int MODE>
__global__ __launch_bounds__(256, 2)
void gemm_fp16(const __half* __restrict__ Ah_g,
               const __half* __restrict__ Wh_g,
               const float* __restrict__ bias,
               float* __restrict__ C,
               __half* __restrict__ Ch,
               int M, int N, int K, float scale, int scale_cols) {
    extern __shared__ __half smg[];

    int tid = threadIdx.x;
    int lane = tid & 31, wid = tid >> 5;
    int warpM = wid & 1, warpN = wid >> 1;
    int m0 = warpM * 64, n0 = warpN * 32;

    int blockM = blockIdx.y * 128;
    int blockN = blockIdx.x * 128;

    int a_row = lane & 15, a_cs = (lane >> 4) * 8;
    int b_row = lane & 7,  b_cs = ((lane >> 3) & 1) * 8;

    float acc[4][4][4];
#pragma unroll
    for (int f = 0; f < 4; ++f)
#pragma unroll
        for (int g = 0; g < 4; ++g)
#pragma unroll
            for (int j = 0; j < 4; ++j) acc[f][g][j] = 0.0f;

    int sr[2], sc[2];
#pragma unroll
    for (int wv = 0; wv < 2; ++wv) {
        int idx = tid + wv * 256;
        sr[wv] = idx >> 2;
        sc[wv] = (idx & 3) * 8;
    }

    auto stage = [&](int kt, int buf) {
        __half* base = smg + buf * BUFE;
#pragma unroll
        for (int wv = 0; wv < 2; ++wv) {
            int r = sr[wv], c8 = sc[wv];
            uint32_t dsm = (uint32_t)__cvta_generic_to_shared(base + r * GLDA + c8);
            size_t ga = (size_t)(blockM + r) * K + kt * 32 + c8;
            size_t gb = (size_t)(blockN + r) * K + kt * 32 + c8;
            cpasync16(dsm,           Ah_g + ga);
            cpasync16(dsm + ARR * 2, Wh_g + gb);
        }
        CP_COMMIT();
    };

    int T = K >> 5;
    stage(0, 0);

    for (int kt = 0; kt < T; ++kt) {
        int buf = kt & 1;
        if (kt + 1 < T) { stage(kt + 1, buf ^ 1); CP_WAIT1(); }
        else            { CP_WAIT0(); }
        __syncthreads();

        __half* Ahs = smg + buf * BUFE;
        __half* Bhs = Ahs + ARR;

#pragma unroll
        for (int kc = 0; kc < 32; kc += 16) {
            unsigned aF[16], bHf[8];
#pragma unroll
            for (int f = 0; f < 4; ++f)
                ldsm4(aF + 4 * f, (unsigned)__cvta_generic_to_shared(
                    Ahs + (m0 + f * 16 + a_row) * GLDA + kc + a_cs));
#pragma unroll
            for (int g = 0; g < 4; ++g)
                ldsm2(bHf + 2 * g, (unsigned)__cvta_generic_to_shared(
                    Bhs + (n0 + g * 8 + b_row) * GLDA + kc + b_cs));
#pragma unroll
            for (int f = 0; f < 4; ++f)
#pragma unroll
                for (int g = 0; g < 4; ++g)
                    mma16816(acc[f][g], aF + 4 * f, bHf + 2 * g);
        }
        __syncthreads();
    }

    // ---- epilogue ----
    bool do_scale = (MODE != 2) && (blockN < scale_cols);
#pragma unroll
    for (int f = 0; f < 4; ++f) {
#pragma unroll
        for (int g = 0; g < 4; ++g) {
            int col = blockN + n0 + g * 8 + (lane & 3) * 2;
            float b0 = bias[col], b1 = bias[col + 1];
#pragma unroll
            for (int half_ = 0; half_ < 2; ++half_) {
                int row = blockM + m0 + f * 16 + (lane >> 2) + half_ * 8;
                float v0 = acc[f][g][half_ * 2 + 0] + b0;
                float v1 = acc[f][g][half_ * 2 + 1] + b1;
                if (MODE == 0) {
                    if (do_scale) { v0 *= scale; v1 *= scale; }
                    *(float2*)&C[(size_t)row * N + col] = make_float2(v0, v1);
                } else if (MODE == 1) {
                    if (do_scale) { v0 *= scale; v1 *= scale; }
                    size_t off = (size_t)row * N + col;
                    *(__half2*)(Ch + off) = __halves2half2(__float2half_rn(v0), __float2half_rn(v1));
                } else {
                    v0 = 0.5f * v0 * (1.0f + erff(v0 * 0.70710678118654752f));
                    v1 = 0.5f * v1 * (1.0f + erff(v1 * 0.70710678118654752f));
                    size_t off = (size_t)row * N + col;
                    *(__half2*)(Ch + off) = __halves2half2(__float2half_rn(v0), __float2half_rn(v1));
                }
            }
        }
    }
}

// ---------------- build x ----------------
__global__ void build_x_kernel(const float* __restrict__ question,
                               const float* __restrict__ vproj,
                               const float* __restrict__ pos_emb,
                               const float* __restrict__ mod_emb,
                               const float* __restrict__ nv_g, const float* __restrict__ nv_b,
                               const float* __restrict__ emb_g, const float* __restrict__ emb_b,
                               float* __restrict__ x,
                               __half* __restrict__ xh) {
    __shared__ float sm[4];
    int row = blockIdx.x;
    int b = row / S_, s = row % S_;
    int i0 = threadIdx.x * 4;
    float4 v;
    if (s < Q_) {
        v = ld4(question + ((size_t)b * Q_ + s) * D_ + i0);
    } else {
        v = ld4(vproj + ((size_t)b * T_ + (s - Q_)) * D_ + i0);
        block_ln(v, i0, nv_g, nv_b, sm);
    }
    float4 pe = ld4(pos_emb + (size_t)s * D_ + i0);
    const float* me_p = mod_emb + (size_t)(s < Q_ ? 0 : 1) * D_ + i0;
    float4 me = ld4(me_p);
    v.x += pe.x + me.x; v.y += pe.y + me.y; v.z += pe.z + me.z; v.w += pe.w + me.w;
    block_ln(v, i0, emb_g, emb_b, sm);
    size_t off = (size_t)row * D_ + i0;
    st4(x + off, v);
    h4_store(xh, off, v);
}

// ---------------- residual + LN ----------------
__global__ void add_ln_kernel(const float* __restrict__ y, const float* __restrict__ res,
                              float* __restrict__ out,
                              __half* __restrict__ oh,
                              const float* __restrict__ g, const float* __restrict__ bta) {
    __shared__ float sm[4];
    int row = blockIdx.x;
    int i0 = threadIdx.x * 4;
    size_t off = (size_t)row * D_ + i0;
    float4 a = ld4(y + off), r = ld4(res + off);
    float4 v = make_float4(a.x + r.x, a.y + r.y, a.z + r.z, a.w + r.w);
    block_ln(v, i0, g, bta, sm);
    st4(out + off, v);
    h4_store(oh, off, v);
}

// ---------------- mma flash attention ----------------
// 128 threads / 4 warps; block = (b,h) x 64-query tile; warp owns 16 query rows.
// Q,K,V fp16 from fused qkv (stride LDQKV); scores/PV via m16n8k16, softmax fp32.
#define AT_STR 72   // halves per smem tile row (64 + 8 pad)

__global__ __launch_bounds__(128)
void attn_mma_kernel(const __half* __restrict__ qkv, const int* __restrict__ mask,
                     __half* __restrict__ ch) {
    __shared__ __half Qs[64 * AT_STR];
    __shared__ __half Ks[64 * AT_STR];
    __shared__ __half Vs[64 * AT_STR];
    __shared__ int ms[64];

    int bh = blockIdx.x;
    int b = bh >> 3, h = bh & 7;
    int q0 = blockIdx.y * 64;
    int tid = threadIdx.x;
    int lane = tid & 31, wid = tid >> 5;
    int m0 = wid * 16;

    const __half* qb = qkv + (size_t)b * S_ * LDQKV + h * DH_;
    const __half* kb = qb + 512;
    const __half* vb = qb + 1024;

    // load Q tile
    for (int idx = tid; idx < 512; idx += 128) {
        int r = idx >> 3, c8 = (idx & 7) * 8;
        *(uint4*)&Qs[r * AT_STR + c8] = *(const uint4*)(qb + (size_t)(q0 + r) * LDQKV + c8);
    }
    __syncthreads();

    int a_row = lane & 15, a_cs = (lane >> 4) * 8;
    int b_row = lane & 7,  b_cs = ((lane >> 3) & 1) * 8;

    unsigned aQ[16];
#pragma unroll
    for (int k = 0; k < 4; ++k)
        ldsm4(aQ + 4 * k, (unsigned)__cvta_generic_to_shared(
            &Qs[(m0 + a_row) * AT_STR + k * 16 + a_cs]));

    float m_[2], l_[2], o[8][4];
    m_[0] = m_[1] = -INFINITY;
    l_[0] = l_[1] = 0.0f;
#pragma unroll
    for (int g = 0; g < 8; ++g)
#pragma unroll
        for (int j = 0; j < 4; ++j) o[g][j] = 0.0f;

    int c2 = (lane & 3) * 2;

    for (int kt = 0; kt < 8; ++kt) {
        int k0 = kt * 64;
        __syncthreads();   // all warps done with previous K/V frags
        for (int idx = tid; idx < 512; idx += 128) {
            int r = idx >> 3, c8 = (idx & 7) * 8;
            *(uint4*)&Ks[r * AT_STR + c8] = *(const uint4*)(kb + (size_t)(k0 + r) * LDQKV + c8);
            *(uint4*)&Vs[r * AT_STR + c8] = *(const uint4*)(vb + (size_t)(k0 + r) * LDQKV + c8);
        }
        if (tid < 64) ms[tid] = mask[b * S_ + k0 + tid];
        __syncthreads();

        // scores: sc[g] = 16x8 tile for keys g*8..g*8+7
        float sc[8][4];
#pragma unroll
        for (int g = 0; g < 8; ++g)
#pragma unroll
            for (int j = 0; j < 4; ++j) sc[g][j] = 0.0f;

#pragma unroll
        for (int k = 0; k < 4; ++k) {
            unsigned bK[16];
#pragma unroll
            for (int g = 0; g < 8; ++g)
                ldsm2(bK + 2 * g, (unsigned)__cvta_generic_to_shared(
                    &Ks[(g * 8 + b_row) * AT_STR + k * 16 + b_cs]));
#pragma unroll
            for (int g = 0; g < 8; ++g)
                mma16816(sc[g], aQ + 4 * k, bK + 2 * g);
        }

        // mask columns
#pragma unroll
        for (int g = 0; g < 8; ++g) {
            if (ms[g * 8 + c2] == 0)     { sc[g][0] = -INFINITY; sc[g][2] = -INFINITY; }
            if (ms[g * 8 + c2 + 1] == 0) { sc[g][1] = -INFINITY; sc[g][3] = -INFINITY; }
        }

        // online softmax per half-row (hr=0: row r, regs 0,1; hr=1: row r+8, regs 2,3)
#pragma unroll
        for (int hr = 0; hr < 2; ++hr) {
            float rmax = -INFINITY;
#pragma unroll
            for (int g = 0; g < 8; ++g)
                rmax = fmaxf(rmax, fmaxf(sc[g][hr * 2], sc[g][hr * 2 + 1]));
            rmax = fmaxf(rmax, __shfl_xor_sync(0xffffffffu, rmax, 1));
            rmax = fmaxf(rmax, __shfl_xor_sync(0xffffffffu, rmax, 2));
            float nm = fmaxf(m_[hr], rmax);
            float corr, psum = 0.0f;
            if (nm == -INFINITY) {
                corr = 1.0f;
#pragma unroll
                for (int g = 0; g < 8; ++g) { sc[g][hr * 2] = 0.0f; sc[g][hr * 2 + 1] = 0.0f; }
            } else {
                corr = __expf(m_[hr] - nm);
#pragma unroll
                for (int g = 0; g < 8; ++g) {
                    float p0 = __expf(sc[g][hr * 2] - nm);
                    float p1 = __expf(sc[g][hr * 2 + 1] - nm);
                    sc[g][hr * 2] = p0; sc[g][hr * 2 + 1] = p1;
                    psum += p0 + p1;
                }
                m_[hr] = nm;
            }
            psum += __shfl_xor_sync(0xffffffffu, psum, 1);
            psum += __shfl_xor_sync(0xffffffffu, psum, 2);
            l_[hr] = l_[hr] * corr + psum;
#pragma unroll
            for (int g = 0; g < 8; ++g) { o[g][hr * 2] *= corr; o[g][hr * 2 + 1] *= corr; }
        }

        // PV: o[g] += P(16 x 64) @ V(64 x dh8[g])
#pragma unroll
        for (int j = 0; j < 4; ++j) {
            unsigned pA[4];
            pA[0] = __half2_raw(__halves2half2(__float2half_rn(sc[2 * j][0]),     __float2half_rn(sc[2 * j][1]))).x
                    | ((unsigned)__half2_raw(__halves2half2(__float2half_rn(sc[2 * j][0]), __float2half_rn(sc[2 * j][1]))).y << 16);
            // (simpler reliable packing below)
            __half2 t0 = __halves2half2(__float2half_rn(sc[2 * j][0]),     __float2half_rn(sc[2 * j][1]));
            __half2 t1 = __halves2half2(__float2half_rn(sc[2 * j][2]),     __float2half_rn(sc[2 * j][3]));
            __half2 t2 = __halves2half2(__float2half_rn(sc[2 * j + 1][0]), __float2half_rn(sc[2 * j + 1][1]));
            __half2 t3 = __halves2half2(__float2half_rn(sc[2 * j + 1][2]), __float2half_rn(sc[2 * j + 1][3]));
            pA[0] = *(unsigned*)&t0;
            pA[1] = *(unsigned*)&t1;
            pA[2] = *(unsigned*)&t2;
            pA[3] = *(unsigned*)&t3;
            unsigned vrow = (unsigned)__cvta_generic_to_shared(
                &Vs[(j * 16 + (lane & 15)) * AT_STR]);
#pragma unroll
            for (int g = 0; g < 8; ++g) {
                unsigned bV[2];
                ldsm2t(bV, vrow + g * 16);   // g*8 halves = 16 bytes
                mma16816(o[g], pA, bV);
            }
        }
    }

    // write ctx: rows m0 + (lane>>2) and +8, cols h*64 + g*8 + c2
    int r_lo = lane >> 2;
#pragma unroll
    for (int hr = 0; hr < 2; ++hr) {
        float inv = (l_[hr] > 0.0f) ? (1.0f / l_[hr]) : 0.0f;
        int row = q0 + m0 + r_lo + hr * 8;
        size_t base = (size_t)(b * S_ + row) * D_ + h * DH_;
#pragma unroll
        for (int g = 0; g < 8; ++g) {
            __half2 hv = __halves2half2(__float2half_rn(o[g][hr * 2] * inv),
                                        __float2half_rn(o[g][hr * 2 + 1] * inv));
            *(__half2*)(ch + base + g * 8 + c2) = hv;
        }
    }
}

// ---------------- launcher ----------------
extern "C" void kernel_launch(void* const* d_in, const int* in_sizes, int n_in,
                              void* d_out, int out_size) {
    const float* video    = (const float*)d_in[0];
    const float* question = (const float*)d_in[1];
    const int*   mask     = (const int*)d_in[2];
    const float* pos_emb  = (const float*)d_in[3];
    const float* mod_emb  = (const float*)d_in[4];
    const float* Wv   = (const float*)d_in[5];
    const float* bv   = (const float*)d_in[6];
    const float* nv_g = (const float*)d_in[7];
    const float* nv_b = (const float*)d_in[8];
    const float* emb_g = (const float*)d_in[9];
    const float* emb_b = (const float*)d_in[10];
    const float* Wq  = (const float*)d_in[11];
    const float* bq  = (const float*)d_in[12];
    const float* Wk  = (const float*)d_in[13];
    const float* bk  = (const float*)d_in[14];
    const float* Wva = (const float*)d_in[15];
    const float* bva = (const float*)d_in[16];
    const float* Wo  = (const float*)d_in[17];
    const float* bo  = (const float*)d_in[18];
    const float* ln1_g = (const float*)d_in[19];
    const float* ln1_b = (const float*)d_in[20];
    const float* W1  = (const float*)d_in[21];
    const float* b1  = (const float*)d_in[22];
    const float* W2  = (const float*)d_in[23];
    const float* b2  = (const float*)d_in[24];
    const float* ln2_g = (const float*)d_in[25];
    const float* ln2_b = (const float*)d_in[26];
    float* out = (float*)d_out;

    float *x, *yb, *vproj, *bqkv;
    __half *wh, *xh, *ch, *hh, *vh, *qkvh;
    cudaGetSymbolAddress((void**)&x,     g_x);
    cudaGetSymbolAddress((void**)&yb,    g_y);
    cudaGetSymbolAddress((void**)&vproj, g_vproj);
    cudaGetSymbolAddress((void**)&bqkv,  g_bqkv);
    cudaGetSymbolAddress((void**)&wh,    g_wh);
    cudaGetSymbolAddress((void**)&xh,    g_xh);
    cudaGetSymbolAddress((void**)&ch,    g_ch);
    cudaGetSymbolAddress((void**)&hh,    g_hh);
    cudaGetSymbolAddress((void**)&vh,    g_vh);
    cudaGetSymbolAddress((void**)&qkvh,  g_qkvh);

    static bool attr_set = false;
    if (!attr_set) {
        cudaFuncSetAttribute(gemm_fp16<0>, cudaFuncAttributeMaxDynamicSharedMemorySize, GT2_SMEM);
        cudaFuncSetAttribute(gemm_fp16<1>, cudaFuncAttributeMaxDynamicSharedMemorySize, GT2_SMEM);
        cudaFuncSetAttribute(gemm_fp16<2>, cudaFuncAttributeMaxDynamicSharedMemorySize, GT2_SMEM);
        attr_set = true;
    }

    const size_t o_wv = 0;
    const size_t LSTRIDE = 4 * (size_t)D_ * D_ + 2 * (size_t)D_ * FF_;
    const size_t o_l0 = o_wv + (size_t)D_ * FD_;
    auto o_wq = [&](int i) { return o_l0 + i * LSTRIDE + 0 * (size_t)D_ * D_; };
    auto o_wk = [&](int i) { return o_l0 + i * LSTRIDE + 1 * (size_t)D_ * D_; };
    auto o_wa = [&](int i) { return o_l0 + i * LSTRIDE + 2 * (size_t)D_ * D_; };
    auto o_wo = [&](int i) { return o_l0 + i * LSTRIDE + 3 * (size_t)D_ * D_; };
    auto o_w1 = [&](int i) { return o_l0 + i * LSTRIDE + 4 * (size_t)D_ * D_; };
    auto o_w2 = [&](int i) { return o_l0 + i * LSTRIDE + 4 * (size_t)D_ * D_ + (size_t)FF_ * D_; };

    split_w_kernel<<<dim3(D_ / 32, FD_ / 32), dim3(32, 8)>>>(Wv, FD_, D_, wh + o_wv);
    for (int i = 0; i < 2; ++i) {
        split_w_kernel<<<dim3(D_ / 32, D_ / 32), dim3(32, 8)>>>(Wq + (size_t)i * D_ * D_, D_, D_, wh + o_wq(i));
        split_w_kernel<<<dim3(D_ / 32, D_ / 32), dim3(32, 8)>>>(Wk + (size_t)i * D_ * D_, D_, D_, wh + o_wk(i));
        split_w_kernel<<<dim3(D_ / 32, D_ / 32), dim3(32, 8)>>>(Wva + (size_t)i * D_ * D_, D_, D_, wh + o_wa(i));
        split_w_kernel<<<dim3(D_ / 32, D_ / 32), dim3(32, 8)>>>(Wo + (size_t)i * D_ * D_, D_, D_, wh + o_wo(i));
        split_w_kernel<<<dim3(FF_ / 32, D_ / 32), dim3(32, 8)>>>(W1 + (size_t)i * D_ * FF_, D_, FF_, wh + o_w1(i));
        split_w_kernel<<<dim3(D_ / 32, FF_ / 32), dim3(32, 8)>>>(W2 + (size_t)i * FF_ * D_, FF_, D_, wh + o_w2(i));
        concat_bias_kernel<<<6, 256>>>(bq + i * D_, bk + i * D_, bva + i * D_, bqkv + i * LDQKV);
    }

    // video convert + projection
    split_a_kernel<<<(BT_ * FD_) / 1024, 256>>>(video, vh);
    gemm_fp16<0><<<dim3(D_ / 128, BT_ / 128), 256, GT2_SMEM>>>(vh, wh + o_wv, bv,
                                                               vproj, nullptr, BT_, D_, FD_, 1.0f, 0);
    build_x_kernel<<<BS_, 128>>>(question, vproj, pos_emb, mod_emb, nv_g, nv_b, emb_g, emb_b, x, xh);

    const float scale = 0.125f;
    for (int i = 0; i < 2; ++i) {
        // fused QKV -> fp16 (Q columns scaled)
        gemm_fp16<1><<<dim3(LDQKV / 128, BS_ / 128), 256, GT2_SMEM>>>(xh, wh + o_wq(i),
                                                                      bqkv + i * LDQKV, nullptr, qkvh,
                                                                      BS_, LDQKV, D_, scale, 512);

        attn_mma_kernel<<<dim3(B_ * H_, S_ / 64), 128>>>(qkvh, mask, ch);

        gemm_fp16<0><<<dim3(D_ / 128, BS_ / 128), 256, GT2_SMEM>>>(ch, wh + o_wo(i), bo + i * D_,
                                                                   yb, nullptr, BS_, D_, D_, 1.0f, 0);
        add_ln_kernel<<<BS_, 128>>>(yb, x, x, xh, ln1_g + i * D_, ln1_b + i * D_);

        gemm_fp16<2><<<dim3(FF_ / 128, BS_ / 128), 256, GT2_SMEM>>>(xh, wh + o_w1(i), b1 + i * FF_,
                                                                    nullptr, hh, BS_, FF_, D_, 1.0f, 0);
        gemm_fp16<0><<<dim3(D_ / 128, BS_ / 128), 256, GT2_SMEM>>>(hh, wh + o_w2(i), b2 + i * D_,
                                                                   yb, nullptr, BS_, D_, FF_, 1.0f, 0);

        float* dst = (i == 1) ? out : x;
        add_ln_kernel<<<BS_, 128>>>(yb, x, dst, xh, ln2_g + i * D_, ln2_b + i * D_);
    }
    (void)in_sizes; (void)n_in; (void)out_size;
}